// round 3
// baseline (speedup 1.0000x reference)
#include <cuda_runtime.h>

// ---------------- problem dims ----------------
constexpr int NB  = 512;    // batch
constexpr int NH  = 512;    // hidden
constexpr int NE  = 512;    // embed dim
constexpr int NV  = 2048;   // vocab
constexpr int NIN = 1024;   // input dim
constexpr int NL  = 32;     // steps
constexpr int NLP = 33;     // steps + EOS

// output layout: tuple (seq, probs, logp, ent) flattened in order, float32
constexpr size_t SEQ_OFF   = 0;
constexpr size_t PROBS_OFF = (size_t)NB * NLP;
constexpr size_t LOGP_OFF  = PROBS_OFF + (size_t)NB * NLP * NV;
constexpr size_t ENT_OFF   = LOGP_OFF + (size_t)NB * NLP;

// ---------------- device state ----------------
__device__ float g_h[NB * NH];
__device__ float g_c[NB * NH];
__device__ float g_e[NB * NE];
__device__ float g_gates[NB * 4 * NH];
__device__ float g_logits[NB * NV];

// ---------------- threefry2x32 (JAX-exact) ----------------
#define TF_ROTL(x, d) (((x) << (d)) | ((x) >> (32 - (d))))
#define TF_ROUND(r) { x0 += x1; x1 = TF_ROTL(x1, r); x1 ^= x0; }

__host__ __device__ __forceinline__ void threefry2x32(
    unsigned int k0, unsigned int k1, unsigned int x0, unsigned int x1,
    unsigned int& o0, unsigned int& o1)
{
    unsigned int ks0 = k0, ks1 = k1, ks2 = k0 ^ k1 ^ 0x1BD11BDAu;
    x0 += ks0; x1 += ks1;
    TF_ROUND(13) TF_ROUND(15) TF_ROUND(26) TF_ROUND(6)
    x0 += ks1; x1 += ks2 + 1u;
    TF_ROUND(17) TF_ROUND(29) TF_ROUND(16) TF_ROUND(24)
    x0 += ks2; x1 += ks0 + 2u;
    TF_ROUND(13) TF_ROUND(15) TF_ROUND(26) TF_ROUND(6)
    x0 += ks0; x1 += ks1 + 3u;
    TF_ROUND(17) TF_ROUND(29) TF_ROUND(16) TF_ROUND(24)
    x0 += ks1; x1 += ks2 + 4u;
    TF_ROUND(13) TF_ROUND(15) TF_ROUND(26) TF_ROUND(6)
    x0 += ks2; x1 += ks0 + 5u;
    o0 = x0; o1 = x1;
}

// ---------------- GEMM: C = A1*B1 (+A2*B2) + bias1 (+bias2) ----------------
// A row-major [M,K], B row-major [K,N], C row-major [M,N]. All dims % 64 == 0, K % 32 == 0.
constexpr int BM = 64, BN = 64, BK = 32;

__global__ __launch_bounds__(64) void gemm_kernel(
    const float* __restrict__ A1, const float* __restrict__ B1, int K1,
    const float* __restrict__ A2, const float* __restrict__ B2, int K2,
    const float* __restrict__ bias1, const float* __restrict__ bias2,
    float* __restrict__ C, int M, int N)
{
    __shared__ float As[BK][BM + 4];
    __shared__ float Bs[BK][BN];
    const int tid = threadIdx.x;
    const int tx = tid & 7;        // N dir (8)
    const int ty = tid >> 3;       // M dir (8)
    const int m0 = blockIdx.y * BM;
    const int n0 = blockIdx.x * BN;

    float acc[8][8];
#pragma unroll
    for (int i = 0; i < 8; i++)
#pragma unroll
        for (int j = 0; j < 8; j++) acc[i][j] = 0.f;

    float ar[8], br[8];

#pragma unroll 1
    for (int src = 0; src < 2; src++) {
        const float* A  = src ? A2 : A1;
        const float* Bw = src ? B2 : B1;
        const int    K  = src ? K2 : K1;
        if (A == nullptr) continue;
#pragma unroll 1
        for (int kt = 0; kt < K; kt += BK) {
            // A tile 64(m) x 32(k) -> transposed into As[k][m]
#pragma unroll
            for (int i = 0; i < 8; i++) {
                int idx = tid * 4 + i * 256;          // float4 granularity over 2048
                int r = idx >> 5, c = idx & 31;       // r: row in tile, c: k offset
                float4 v = *(const float4*)(A + (size_t)(m0 + r) * K + kt + c);
                As[c + 0][r] = v.x; As[c + 1][r] = v.y;
                As[c + 2][r] = v.z; As[c + 3][r] = v.w;
            }
            // B tile 32(k) x 64(n)
#pragma unroll
            for (int i = 0; i < 8; i++) {
                int idx = tid * 4 + i * 256;
                int r = idx >> 6, c = idx & 63;
                *(float4*)&Bs[r][c] =
                    *(const float4*)(Bw + (size_t)(kt + r) * N + n0 + c);
            }
            __syncthreads();
#pragma unroll
            for (int kk = 0; kk < BK; kk++) {
                *(float4*)&ar[0] = *(const float4*)&As[kk][ty * 8];
                *(float4*)&ar[4] = *(const float4*)&As[kk][ty * 8 + 4];
                *(float4*)&br[0] = *(const float4*)&Bs[kk][tx * 8];
                *(float4*)&br[4] = *(const float4*)&Bs[kk][tx * 8 + 4];
#pragma unroll
                for (int i = 0; i < 8; i++)
#pragma unroll
                    for (int j = 0; j < 8; j++)
                        acc[i][j] = fmaf(ar[i], br[j], acc[i][j]);
            }
            __syncthreads();
        }
    }

    // epilogue: bias add (bias2 optional), vectorized stores
    float bsum[8];
#pragma unroll
    for (int j = 0; j < 8; j++) {
        int n = n0 + tx * 8 + j;
        float bv = bias1 ? bias1[n] : 0.f;
        if (bias2) bv += bias2[n];
        bsum[j] = bv;
    }
#pragma unroll
    for (int i = 0; i < 8; i++) {
        int m = m0 + ty * 8 + i;
        float4 v0, v1;
        v0.x = acc[i][0] + bsum[0]; v0.y = acc[i][1] + bsum[1];
        v0.z = acc[i][2] + bsum[2]; v0.w = acc[i][3] + bsum[3];
        v1.x = acc[i][4] + bsum[4]; v1.y = acc[i][5] + bsum[5];
        v1.z = acc[i][6] + bsum[6]; v1.w = acc[i][7] + bsum[7];
        float* cp = C + (size_t)m * N + n0 + tx * 8;
        *(float4*)(cp)     = v0;
        *(float4*)(cp + 4) = v1;
    }
}

// ---------------- init: c = 0, e = broadcast(sos) ----------------
__global__ void init_kernel(const float* __restrict__ sos)
{
    int idx = blockIdx.x * blockDim.x + threadIdx.x;
    if (idx >= NB * NE) return;
    g_c[idx] = 0.f;
    g_e[idx] = sos[idx & (NE - 1)];
}

// ---------------- EOS step outputs ----------------
__global__ void eos_kernel(float* __restrict__ out)
{
    int idx = blockIdx.x * blockDim.x + threadIdx.x;
    if (idx >= NB * NV) return;
    int b = idx >> 11, v = idx & (NV - 1);
    out[PROBS_OFF + ((size_t)b * NLP + NL) * NV + v] = 1.0f;
    if (v == 0) {
        out[SEQ_OFF  + (size_t)b * NLP + NL] = 0.f;
        out[LOGP_OFF + (size_t)b * NLP + NL] = 0.f;
        out[ENT_OFF  + (size_t)b * NLP + NL] = 0.f;
    }
}

// ---------------- LSTM cell elementwise ----------------
__global__ void cell_kernel()
{
    int idx = blockIdx.x * blockDim.x + threadIdx.x;
    if (idx >= NB * NH) return;
    int b = idx >> 9, hd = idx & (NH - 1);
    const float* gr = g_gates + (size_t)b * (4 * NH);
    float ig = 1.f / (1.f + expf(-gr[hd]));
    float fg = 1.f / (1.f + expf(-gr[NH + hd]));
    float gg = tanhf(gr[2 * NH + hd]);
    float og = 1.f / (1.f + expf(-gr[3 * NH + hd]));
    float c = fg * g_c[idx] + ig * gg;
    float h = og * tanhf(c);
    g_c[idx] = c;
    g_h[idx] = h;
}

// ---------------- log_softmax + entropy + gumbel sample + embed gather ----------------
__global__ __launch_bounds__(256) void sampler_kernel(
    const float* __restrict__ logits, const float* __restrict__ emb,
    float* __restrict__ out, int t, unsigned int sk0, unsigned int sk1)
{
    __shared__ float row[NV];
    __shared__ float sred[256];
    __shared__ float sbest[256];
    __shared__ int   sbi[256];
    __shared__ float s_max, s_lse;
    __shared__ int   s_sym;

    const int b = blockIdx.x;
    const int tid = threadIdx.x;

    const float* lrow = logits + (size_t)b * NV;
    for (int v = tid; v < NV; v += 256) row[v] = lrow[v];
    __syncthreads();

    // row max
    float m = -3.402823466e38f;
    for (int v = tid; v < NV; v += 256) m = fmaxf(m, row[v]);
    sred[tid] = m;
    __syncthreads();
    for (int s = 128; s > 0; s >>= 1) {
        if (tid < s) sred[tid] = fmaxf(sred[tid], sred[tid + s]);
        __syncthreads();
    }
    if (tid == 0) s_max = sred[0];
    __syncthreads();
    const float xmax = s_max;

    // log-sum-exp
    float sum = 0.f;
    for (int v = tid; v < NV; v += 256) sum += expf(row[v] - xmax);
    sred[tid] = sum;
    __syncthreads();
    for (int s = 128; s > 0; s >>= 1) {
        if (tid < s) sred[tid] += sred[tid + s];
        __syncthreads();
    }
    if (tid == 0) s_lse = logf(sred[0]);
    __syncthreads();
    const float lse = s_lse;

    // main pass: probs, entropy, gumbel argmax
    float entacc = 0.f;
    float best = -3.402823466e38f;
    int besti = NV;
    float* probs_out = out + PROBS_OFF + ((size_t)b * NLP + t) * NV;
    for (int v = tid; v < NV; v += 256) {
        float ls = (row[v] - xmax) - lse;
        float p = expf(ls);
        probs_out[v] = p;
        entacc += p * ls;
        // JAX partitionable threefry bits: counter = flat index (hi=0, lo=j), bits = o0^o1
        unsigned int o0, o1;
        threefry2x32(sk0, sk1, 0u, (unsigned int)(b * NV + v), o0, o1);
        unsigned int bits = o0 ^ o1;
        float f = __uint_as_float((bits >> 9) | 0x3f800000u) - 1.0f;
        float u = fmaxf(1.17549435e-38f, f + 1.17549435e-38f);
        float g = -logf(-logf(u));
        float score = g + ls;
        if (score > best) { best = score; besti = v; }
    }
    sred[tid] = entacc; sbest[tid] = best; sbi[tid] = besti;
    __syncthreads();
    for (int s = 128; s > 0; s >>= 1) {
        if (tid < s) {
            sred[tid] += sred[tid + s];
            float ob = sbest[tid + s]; int oi = sbi[tid + s];
            if (ob > sbest[tid] || (ob == sbest[tid] && oi < sbi[tid])) {
                sbest[tid] = ob; sbi[tid] = oi;
            }
        }
        __syncthreads();
    }
    if (tid == 0) {
        int sym = sbi[0];
        s_sym = sym;
        out[SEQ_OFF  + (size_t)b * NLP + t] = (float)sym;
        out[ENT_OFF  + (size_t)b * NLP + t] = -sred[0];
        out[LOGP_OFF + (size_t)b * NLP + t] = (row[sym] - xmax) - lse;
    }
    __syncthreads();
    const int sym = s_sym;
    for (int i = tid; i < NE; i += 256)
        g_e[(size_t)b * NE + i] = emb[(size_t)sym * NE + i];
}

// ---------------- launch ----------------
extern "C" void kernel_launch(void* const* d_in, const int* in_sizes, int n_in,
                              void* d_out, int out_size)
{
    (void)in_sizes; (void)n_in; (void)out_size;
    const float* x         = (const float*)d_in[0];
    const float* agent_w   = (const float*)d_in[1];
    const float* agent_b   = (const float*)d_in[2];
    const float* sos       = (const float*)d_in[3];
    const float* embedding = (const float*)d_in[4];
    const float* w_ih      = (const float*)d_in[5];
    const float* w_hh      = (const float*)d_in[6];
    const float* b_ih      = (const float*)d_in[7];
    const float* b_hh      = (const float*)d_in[8];
    const float* out_w     = (const float*)d_in[9];
    const float* out_b     = (const float*)d_in[10];
    float* out = (float*)d_out;

    float *ph, *pc, *pe, *pg, *pl;
    cudaGetSymbolAddress((void**)&ph, g_h);
    cudaGetSymbolAddress((void**)&pc, g_c);
    cudaGetSymbolAddress((void**)&pe, g_e);
    cudaGetSymbolAddress((void**)&pg, g_gates);
    cudaGetSymbolAddress((void**)&pl, g_logits);
    (void)pc;

    // host-side key chain: key(1) = (0,1); fold-like split per step
    unsigned int key0 = 0u, key1 = 1u;
    unsigned int sk0[NL], sk1[NL];
    for (int t = 0; t < NL; t++) {
        unsigned int n0, n1, s0, s1;
        threefry2x32(key0, key1, 0u, 0u, n0, n1);  // new carry key
        threefry2x32(key0, key1, 0u, 1u, s0, s1);  // subkey for this step
        sk0[t] = s0; sk1[t] = s1;
        key0 = n0; key1 = n1;
    }

    init_kernel<<<(NB * NE + 255) / 256, 256>>>(sos);
    eos_kernel<<<(NB * NV + 255) / 256, 256>>>(out);

    // h0 = x @ agent_w + agent_b   [512,1024]@[1024,512]
    gemm_kernel<<<dim3(NH / BN, NB / BM), 64>>>(
        x, agent_w, NIN, nullptr, nullptr, 0, agent_b, nullptr, ph, NB, NH);

    for (int t = 0; t < NL; t++) {
        // gates = e@w_ih + h@w_hh + (b_ih + b_hh)   [512,2048]
        gemm_kernel<<<dim3(4 * NH / BN, NB / BM), 64>>>(
            pe, w_ih, NE, ph, w_hh, NH, b_ih, b_hh, pg, NB, 4 * NH);
        cell_kernel<<<(NB * NH + 255) / 256, 256>>>();
        // logits = h @ out_w + out_b   [512,2048]
        gemm_kernel<<<dim3(NV / BN, NB / BM), 64>>>(
            ph, out_w, NH, nullptr, nullptr, 0, out_b, nullptr, pl, NB, NV);
        sampler_kernel<<<NB, 256>>>(pl, embedding, out, t, sk0[t], sk1[t]);
    }
}

// round 5
// speedup vs baseline: 1.0494x; 1.0494x over previous
#include <cuda_runtime.h>

// ---------------- problem dims ----------------
constexpr int NB  = 512;    // batch
constexpr int NH  = 512;    // hidden
constexpr int NE  = 512;    // embed dim
constexpr int NV  = 2048;   // vocab
constexpr int NIN = 1024;   // input dim
constexpr int NL  = 32;     // steps
constexpr int NLP = 33;     // steps + EOS

// output layout: tuple (seq, probs, logp, ent) flattened in order, float32
constexpr size_t SEQ_OFF   = 0;
constexpr size_t PROBS_OFF = (size_t)NB * NLP;
constexpr size_t LOGP_OFF  = PROBS_OFF + (size_t)NB * NLP * NV;
constexpr size_t ENT_OFF   = LOGP_OFF + (size_t)NB * NLP;

// ---------------- device state ----------------
__device__ float g_h[NB * NH];
__device__ float g_c[NB * NH];
__device__ float g_e[NB * NE];
__device__ float g_gates[NB * 4 * NH];
__device__ float g_logits[NB * NV];

// ---------------- threefry2x32 (JAX-exact) ----------------
#define TF_ROTL(x, d) (((x) << (d)) | ((x) >> (32 - (d))))
#define TF_ROUND(r) { x0 += x1; x1 = TF_ROTL(x1, r); x1 ^= x0; }

__host__ __device__ __forceinline__ void threefry2x32(
    unsigned int k0, unsigned int k1, unsigned int x0, unsigned int x1,
    unsigned int& o0, unsigned int& o1)
{
    unsigned int ks0 = k0, ks1 = k1, ks2 = k0 ^ k1 ^ 0x1BD11BDAu;
    x0 += ks0; x1 += ks1;
    TF_ROUND(13) TF_ROUND(15) TF_ROUND(26) TF_ROUND(6)
    x0 += ks1; x1 += ks2 + 1u;
    TF_ROUND(17) TF_ROUND(29) TF_ROUND(16) TF_ROUND(24)
    x0 += ks2; x1 += ks0 + 2u;
    TF_ROUND(13) TF_ROUND(15) TF_ROUND(26) TF_ROUND(6)
    x0 += ks0; x1 += ks1 + 3u;
    TF_ROUND(17) TF_ROUND(29) TF_ROUND(16) TF_ROUND(24)
    x0 += ks1; x1 += ks2 + 4u;
    TF_ROUND(13) TF_ROUND(15) TF_ROUND(26) TF_ROUND(6)
    x0 += ks2; x1 += ks0 + 5u;
    o0 = x0; o1 = x1;
}

// ---------------- GEMM: C = A1*B1 (+A2*B2) + bias1 (+bias2) ----------------
// A row-major [M,K], B row-major [K,N], C row-major [M,N]. All dims % 64 == 0, K % 32 == 0.
constexpr int BM = 64, BN = 64, BK = 32;

__global__ __launch_bounds__(64) void gemm_kernel(
    const float* __restrict__ A1, const float* __restrict__ B1, int K1,
    const float* __restrict__ A2, const float* __restrict__ B2, int K2,
    const float* __restrict__ bias1, const float* __restrict__ bias2,
    float* __restrict__ C, int M, int N)
{
    __shared__ float As[BK][BM + 4];
    __shared__ float Bs[BK][BN];
    const int tid = threadIdx.x;
    const int tx = tid & 7;        // N dir (8)
    const int ty = tid >> 3;       // M dir (8)
    const int m0 = blockIdx.y * BM;
    const int n0 = blockIdx.x * BN;

    float acc[8][8];
#pragma unroll
    for (int i = 0; i < 8; i++)
#pragma unroll
        for (int j = 0; j < 8; j++) acc[i][j] = 0.f;

    float ar[8], br[8];

#pragma unroll 1
    for (int src = 0; src < 2; src++) {
        const float* A  = src ? A2 : A1;
        const float* Bw = src ? B2 : B1;
        const int    K  = src ? K2 : K1;
        if (A == nullptr) continue;
#pragma unroll 1
        for (int kt = 0; kt < K; kt += BK) {
            // A tile 64(m) x 32(k) -> transposed into As[k][m]
#pragma unroll
            for (int i = 0; i < 8; i++) {
                int idx = tid * 4 + i * 256;          // float4 granularity over 2048
                int r = idx >> 5, c = idx & 31;       // r: row in tile, c: k offset
                float4 v = *(const float4*)(A + (size_t)(m0 + r) * K + kt + c);
                As[c + 0][r] = v.x; As[c + 1][r] = v.y;
                As[c + 2][r] = v.z; As[c + 3][r] = v.w;
            }
            // B tile 32(k) x 64(n)
#pragma unroll
            for (int i = 0; i < 8; i++) {
                int idx = tid * 4 + i * 256;
                int r = idx >> 6, c = idx & 63;
                *(float4*)&Bs[r][c] =
                    *(const float4*)(Bw + (size_t)(kt + r) * N + n0 + c);
            }
            __syncthreads();
#pragma unroll
            for (int kk = 0; kk < BK; kk++) {
                *(float4*)&ar[0] = *(const float4*)&As[kk][ty * 8];
                *(float4*)&ar[4] = *(const float4*)&As[kk][ty * 8 + 4];
                *(float4*)&br[0] = *(const float4*)&Bs[kk][tx * 8];
                *(float4*)&br[4] = *(const float4*)&Bs[kk][tx * 8 + 4];
#pragma unroll
                for (int i = 0; i < 8; i++)
#pragma unroll
                    for (int j = 0; j < 8; j++)
                        acc[i][j] = fmaf(ar[i], br[j], acc[i][j]);
            }
            __syncthreads();
        }
    }

    // epilogue: bias add (bias2 optional), vectorized stores
    float bsum[8];
#pragma unroll
    for (int j = 0; j < 8; j++) {
        int n = n0 + tx * 8 + j;
        float bv = bias1 ? bias1[n] : 0.f;
        if (bias2) bv += bias2[n];
        bsum[j] = bv;
    }
#pragma unroll
    for (int i = 0; i < 8; i++) {
        int m = m0 + ty * 8 + i;
        float4 v0, v1;
        v0.x = acc[i][0] + bsum[0]; v0.y = acc[i][1] + bsum[1];
        v0.z = acc[i][2] + bsum[2]; v0.w = acc[i][3] + bsum[3];
        v1.x = acc[i][4] + bsum[4]; v1.y = acc[i][5] + bsum[5];
        v1.z = acc[i][6] + bsum[6]; v1.w = acc[i][7] + bsum[7];
        float* cp = C + (size_t)m * N + n0 + tx * 8;
        *(float4*)(cp)     = v0;
        *(float4*)(cp + 4) = v1;
    }
}

// ---------------- init: c = 0, e = broadcast(sos) ----------------
__global__ void init_kernel(const float* __restrict__ sos)
{
    int idx = blockIdx.x * blockDim.x + threadIdx.x;
    if (idx >= NB * NE) return;
    g_c[idx] = 0.f;
    g_e[idx] = sos[idx & (NE - 1)];
}

// ---------------- EOS step outputs ----------------
__global__ void eos_kernel(float* __restrict__ out)
{
    int idx = blockIdx.x * blockDim.x + threadIdx.x;
    if (idx >= NB * NV) return;
    int b = idx >> 11, v = idx & (NV - 1);
    out[PROBS_OFF + ((size_t)b * NLP + NL) * NV + v] = 1.0f;
    if (v == 0) {
        out[SEQ_OFF  + (size_t)b * NLP + NL] = 0.f;
        out[LOGP_OFF + (size_t)b * NLP + NL] = 0.f;
        out[ENT_OFF  + (size_t)b * NLP + NL] = 0.f;
    }
}

// ---------------- LSTM cell elementwise ----------------
__global__ void cell_kernel()
{
    int idx = blockIdx.x * blockDim.x + threadIdx.x;
    if (idx >= NB * NH) return;
    int b = idx >> 9, hd = idx & (NH - 1);
    const float* gr = g_gates + (size_t)b * (4 * NH);
    float ig = 1.f / (1.f + expf(-gr[hd]));
    float fg = 1.f / (1.f + expf(-gr[NH + hd]));
    float gg = tanhf(gr[2 * NH + hd]);
    float og = 1.f / (1.f + expf(-gr[3 * NH + hd]));
    float c = fg * g_c[idx] + ig * gg;
    float h = og * tanhf(c);
    g_c[idx] = c;
    g_h[idx] = h;
}

// ---------------- log_softmax + entropy + gumbel sample + embed gather ----------------
__global__ __launch_bounds__(256) void sampler_kernel(
    const float* __restrict__ logits, const float* __restrict__ emb,
    float* __restrict__ out, int t, unsigned int sk0, unsigned int sk1)
{
    __shared__ float row[NV];
    __shared__ float sred[256];
    __shared__ float sbest[256];
    __shared__ int   sbi[256];
    __shared__ float s_max, s_lse;
    __shared__ int   s_sym;

    const int b = blockIdx.x;
    const int tid = threadIdx.x;

    const float* lrow = logits + (size_t)b * NV;
    for (int v = tid; v < NV; v += 256) row[v] = lrow[v];
    __syncthreads();

    // row max
    float m = -3.402823466e38f;
    for (int v = tid; v < NV; v += 256) m = fmaxf(m, row[v]);
    sred[tid] = m;
    __syncthreads();
    for (int s = 128; s > 0; s >>= 1) {
        if (tid < s) sred[tid] = fmaxf(sred[tid], sred[tid + s]);
        __syncthreads();
    }
    if (tid == 0) s_max = sred[0];
    __syncthreads();
    const float xmax = s_max;

    // log-sum-exp
    float sum = 0.f;
    for (int v = tid; v < NV; v += 256) sum += expf(row[v] - xmax);
    sred[tid] = sum;
    __syncthreads();
    for (int s = 128; s > 0; s >>= 1) {
        if (tid < s) sred[tid] += sred[tid + s];
        __syncthreads();
    }
    if (tid == 0) s_lse = logf(sred[0]);
    __syncthreads();
    const float lse = s_lse;

    // main pass: probs, entropy, gumbel argmax
    float entacc = 0.f;
    float best = -3.402823466e38f;
    int besti = NV;
    float* probs_out = out + PROBS_OFF + ((size_t)b * NLP + t) * NV;
    for (int v = tid; v < NV; v += 256) {
        float ls = (row[v] - xmax) - lse;
        float p = expf(ls);
        probs_out[v] = p;
        entacc += p * ls;
        // JAX partitionable threefry bits: counter = flat index (hi=0, lo=j), bits = o0^o1
        unsigned int o0, o1;
        threefry2x32(sk0, sk1, 0u, (unsigned int)(b * NV + v), o0, o1);
        unsigned int bits = o0 ^ o1;
        float f = __uint_as_float((bits >> 9) | 0x3f800000u) - 1.0f;
        float u = fmaxf(1.17549435e-38f, f + 1.17549435e-38f);
        float g = -logf(-logf(u));
        float score = g + ls;
        if (score > best) { best = score; besti = v; }
    }
    sred[tid] = entacc; sbest[tid] = best; sbi[tid] = besti;
    __syncthreads();
    for (int s = 128; s > 0; s >>= 1) {
        if (tid < s) {
            sred[tid] += sred[tid + s];
            float ob = sbest[tid + s]; int oi = sbi[tid + s];
            if (ob > sbest[tid] || (ob == sbest[tid] && oi < sbi[tid])) {
                sbest[tid] = ob; sbi[tid] = oi;
            }
        }
        __syncthreads();
    }
    if (tid == 0) {
        int sym = sbi[0];
        s_sym = sym;
        out[SEQ_OFF  + (size_t)b * NLP + t] = (float)sym;
        out[ENT_OFF  + (size_t)b * NLP + t] = -sred[0];
        out[LOGP_OFF + (size_t)b * NLP + t] = (row[sym] - xmax) - lse;
    }
    __syncthreads();
    const int sym = s_sym;
    for (int i = tid; i < NE; i += 256)
        g_e[(size_t)b * NE + i] = emb[(size_t)sym * NE + i];
}

// ---------------- launch ----------------
extern "C" void kernel_launch(void* const* d_in, const int* in_sizes, int n_in,
                              void* d_out, int out_size)
{
    (void)in_sizes; (void)n_in; (void)out_size;
    const float* x         = (const float*)d_in[0];
    const float* agent_w   = (const float*)d_in[1];
    const float* agent_b   = (const float*)d_in[2];
    const float* sos       = (const float*)d_in[3];
    const float* embedding = (const float*)d_in[4];
    const float* w_ih      = (const float*)d_in[5];
    const float* w_hh      = (const float*)d_in[6];
    const float* b_ih      = (const float*)d_in[7];
    const float* b_hh      = (const float*)d_in[8];
    const float* out_w     = (const float*)d_in[9];
    const float* out_b     = (const float*)d_in[10];
    float* out = (float*)d_out;

    float *ph, *pc, *pe, *pg, *pl;
    cudaGetSymbolAddress((void**)&ph, g_h);
    cudaGetSymbolAddress((void**)&pc, g_c);
    cudaGetSymbolAddress((void**)&pe, g_e);
    cudaGetSymbolAddress((void**)&pg, g_gates);
    cudaGetSymbolAddress((void**)&pl, g_logits);
    (void)pc;

    // host-side key chain: key(1) = (0,1); fold-like split per step
    unsigned int key0 = 0u, key1 = 1u;
    unsigned int sk0[NL], sk1[NL];
    for (int t = 0; t < NL; t++) {
        unsigned int n0, n1, s0, s1;
        threefry2x32(key0, key1, 0u, 0u, n0, n1);  // new carry key
        threefry2x32(key0, key1, 0u, 1u, s0, s1);  // subkey for this step
        sk0[t] = s0; sk1[t] = s1;
        key0 = n0; key1 = n1;
    }

    init_kernel<<<(NB * NE + 255) / 256, 256>>>(sos);
    eos_kernel<<<(NB * NV + 255) / 256, 256>>>(out);

    // h0 = x @ agent_w + agent_b   [512,1024]@[1024,512]
    gemm_kernel<<<dim3(NH / BN, NB / BM), 64>>>(
        x, agent_w, NIN, nullptr, nullptr, 0, agent_b, nullptr, ph, NB, NH);

    for (int t = 0; t < NL; t++) {
        // gates = e@w_ih + h@w_hh + (b_ih + b_hh)   [512,2048]
        gemm_kernel<<<dim3(4 * NH / BN, NB / BM), 64>>>(
            pe, w_ih, NE, ph, w_hh, NH, b_ih, b_hh, pg, NB, 4 * NH);
        cell_kernel<<<(NB * NH + 255) / 256, 256>>>();
        // logits = h @ out_w + out_b   [512,2048]
        gemm_kernel<<<dim3(NV / BN, NB / BM), 64>>>(
            ph, out_w, NH, nullptr, nullptr, 0, out_b, nullptr, pl, NB, NV);
        sampler_kernel<<<NB, 256>>>(pl, embedding, out, t, sk0[t], sk1[t]);
    }
}

// round 11
// speedup vs baseline: 2.6769x; 2.5508x over previous
#include <cuda_runtime.h>
#include <cuda_bf16.h>
#include <cstdint>

constexpr int NB=512, NH=512, NE=512, NV=2048, NIN=1024, NL=32, NLP=33;
constexpr size_t SEQ_OFF=0;
constexpr size_t PROBS_OFF=(size_t)NB*NLP;
constexpr size_t LOGP_OFF=PROBS_OFF+(size_t)NB*NLP*NV;
constexpr size_t ENT_OFF=LOGP_OFF+(size_t)NB*NLP;

// plane strides (elements)
constexpr size_t GPS=(size_t)NV*1024;   // gatesWT [2048][1024]
constexpr size_t OPS=(size_t)NV*512;    // outWT   [2048][512]
constexpr size_t APS=(size_t)NH*1024;   // agentWT [512][1024]
constexpr size_t XPS=(size_t)NB*NIN;    // xS      [512][1024]
constexpr size_t EHPS=(size_t)NB*1024;  // ehS     [512][1024] = [e|h]
constexpr size_t EPS=(size_t)NV*NE;     // embS    [2048][512]

__device__ __align__(16) unsigned short g_gatesWT[3*GPS];
__device__ __align__(16) unsigned short g_outWT[3*OPS];
__device__ __align__(16) unsigned short g_agentWT[3*APS];
__device__ __align__(16) unsigned short g_xS[3*XPS];
__device__ __align__(16) unsigned short g_ehS[3*EHPS];
__device__ __align__(16) unsigned short g_embS[3*EPS];
__device__ float g_bias[4*NH];
__device__ float g_h0[NB*NH];
__device__ float g_c[NB*NH];
__device__ float g_gates[NB*4*NH];
__device__ float g_logits[NB*NV];

__device__ __forceinline__ void split3(float v, unsigned short& o0,
                                       unsigned short& o1, unsigned short& o2)
{
    __nv_bfloat16 b0=__float2bfloat16_rn(v);
    float r=v-__bfloat162float(b0);
    __nv_bfloat16 b1=__float2bfloat16_rn(r);
    float r2=r-__bfloat162float(b1);
    __nv_bfloat16 b2=__float2bfloat16_rn(r2);
    o0=__bfloat16_as_ushort(b0); o1=__bfloat16_as_ushort(b1); o2=__bfloat16_as_ushort(b2);
}

// ---------- threefry2x32 (JAX-exact, verified) ----------
#define TF_ROTL(x,d) (((x)<<(d))|((x)>>(32-(d))))
#define TF_ROUND(r) { x0+=x1; x1=TF_ROTL(x1,r); x1^=x0; }
__host__ __device__ __forceinline__ void threefry2x32(
    unsigned int k0,unsigned int k1,unsigned int x0,unsigned int x1,
    unsigned int& o0,unsigned int& o1)
{
    unsigned int ks0=k0,ks1=k1,ks2=k0^k1^0x1BD11BDAu;
    x0+=ks0; x1+=ks1;
    TF_ROUND(13) TF_ROUND(15) TF_ROUND(26) TF_ROUND(6)
    x0+=ks1; x1+=ks2+1u;
    TF_ROUND(17) TF_ROUND(29) TF_ROUND(16) TF_ROUND(24)
    x0+=ks2; x1+=ks0+2u;
    TF_ROUND(13) TF_ROUND(15) TF_ROUND(26) TF_ROUND(6)
    x0+=ks0; x1+=ks1+3u;
    TF_ROUND(17) TF_ROUND(29) TF_ROUND(16) TF_ROUND(24)
    x0+=ks1; x1+=ks2+4u;
    TF_ROUND(13) TF_ROUND(15) TF_ROUND(26) TF_ROUND(6)
    x0+=ks2; x1+=ks0+5u;
    o0=x0; o1=x1;
}

__device__ __forceinline__ uint32_t smem_u32(const void* p)
{ uint32_t a; asm("{ .reg .u64 t; cvta.to.shared.u64 t, %1; cvt.u32.u64 %0, t; }":"=r"(a):"l"(p)); return a; }

__device__ __forceinline__ uint32_t sw128(uint32_t off)
{ return off ^ ((off >> 3) & 0x70u); }

// ---------- portable tensor-core bf16x3 GEMM (mma.sync, sm_80+ ISA) ----------
// C[M,N] fp32 = sum_{6 split products} A[M,K] * B[N,K]^T + bias[N]
// Block tile 64(M) x 128(N), 8 warps (2x4), warp tile 32x32, K staged 64-wide.
// Stage holds ALL 3 A-planes + ALL 3 B-planes; products share staged tiles.
constexpr int APL   = 64*64*2;            // 8192 B per A plane tile
constexpr int BPL   = 128*64*2;           // 16384 B per B plane tile
constexpr int STAGE = 3*APL + 3*BPL;      // 73728 B
constexpr int GSMEM = 2*STAGE;            // 147456 B

__global__ __launch_bounds__(256) void gemm_mma(
    const unsigned short* __restrict__ a0,const unsigned short* __restrict__ a1,
    const unsigned short* __restrict__ a2,int lda,
    const unsigned short* __restrict__ b0,const unsigned short* __restrict__ b1,
    const unsigned short* __restrict__ b2,int ldb,
    int K,float* __restrict__ C,int ldc,const float* __restrict__ bias)
{
    extern __shared__ char sm[];
    const int tid=threadIdx.x, wid=tid>>5, lane=tid&31;
    const int m0=blockIdx.y*64, n0=blockIdx.x*128;
    const int warpM=wid&1, warpN=wid>>1;
    const uint32_t sbase=smem_u32(sm);
    const unsigned short* Ap[3]={a0,a1,a2};
    const unsigned short* Bp[3]={b0,b1,b2};
    const int KT=K>>6;

    float acc[2][4][4];
#pragma unroll
    for(int i=0;i<2;i++)
#pragma unroll
        for(int j=0;j<4;j++)
#pragma unroll
            for(int k=0;k<4;k++) acc[i][j][k]=0.f;

    // ldmatrix lane-address components (within-tile)
    const int aRow = warpM*32 + (lane&7) + ((lane>>3)&1)*8;  // + mf*16
    const int aColL = ((lane>>4)&1)*8;                       // + kk*16
    const int l16 = lane&15;
    const int bRow = warpN*32 + (l16&7);                     // + nf*8
    const int bColL = ((l16>>3)&1)*8;                        // + kk*16

    // ---- cp.async stage issue ----
    auto issue=[&](int kt,int buf){
        uint32_t st=sbase+(uint32_t)buf*STAGE;
#pragma unroll
        for(int i=0;i<18;i++){
            int idx=tid+i*256;
            const unsigned short* g; uint32_t so;
            if(idx<1536){                 // A planes: 3 x 512 chunks
                int p=idx>>9, rem=idx&511, r=rem>>3, c8=rem&7;
                g=Ap[p]+(size_t)(m0+r)*lda+kt*64+c8*8;
                so=(uint32_t)p*APL + sw128((uint32_t)r*128+(uint32_t)c8*16);
            }else{                        // B planes: 3 x 1024 chunks
                int j=idx-1536, p=j>>10, rem=j&1023, r=rem>>3, c8=rem&7;
                g=Bp[p]+(size_t)(n0+r)*ldb+kt*64+c8*8;
                so=(uint32_t)(3*APL)+(uint32_t)p*BPL + sw128((uint32_t)r*128+(uint32_t)c8*16);
            }
            asm volatile("cp.async.cg.shared.global [%0],[%1],16;\n"
                         ::"r"(st+so),"l"(g));
        }
        asm volatile("cp.async.commit_group;\n":::"memory");
    };

    issue(0,0);

#pragma unroll 1
    for(int kt=0;kt<KT;kt++){
        if(kt+1<KT){
            issue(kt+1,(kt+1)&1);
            asm volatile("cp.async.wait_group 1;\n":::"memory");
        }else{
            asm volatile("cp.async.wait_group 0;\n":::"memory");
        }
        __syncthreads();

        const uint32_t st=sbase+(uint32_t)(kt&1)*STAGE;
#pragma unroll
        for(int kk=0;kk<4;kk++){
            uint32_t af[3][2][4], bf[3][4][2];
#pragma unroll
            for(int p=0;p<3;p++){
#pragma unroll
                for(int mf=0;mf<2;mf++){
                    uint32_t addr=st+(uint32_t)p*APL+
                        sw128((uint32_t)(aRow+mf*16)*128+(uint32_t)(kk*16+aColL)*2);
                    asm volatile("ldmatrix.sync.aligned.m8n8.x4.shared.b16 {%0,%1,%2,%3},[%4];"
                        :"=r"(af[p][mf][0]),"=r"(af[p][mf][1]),
                         "=r"(af[p][mf][2]),"=r"(af[p][mf][3]):"r"(addr));
                }
#pragma unroll
                for(int nf=0;nf<4;nf++){
                    uint32_t addr=st+(uint32_t)(3*APL)+(uint32_t)p*BPL+
                        sw128((uint32_t)(bRow+nf*8)*128+(uint32_t)(kk*16+bColL)*2);
                    asm volatile("ldmatrix.sync.aligned.m8n8.x2.shared.b16 {%0,%1},[%2];"
                        :"=r"(bf[p][nf][0]),"=r"(bf[p][nf][1]):"r"(addr));
                }
            }
            const int PA[6]={0,0,1,1,0,2};
            const int PB[6]={0,1,0,1,2,0};
#pragma unroll
            for(int t=0;t<6;t++){
#pragma unroll
                for(int mf=0;mf<2;mf++)
#pragma unroll
                    for(int nf=0;nf<4;nf++){
                        asm volatile(
                            "mma.sync.aligned.m16n8k16.row.col.f32.bf16.bf16.f32 "
                            "{%0,%1,%2,%3},{%4,%5,%6,%7},{%8,%9},{%0,%1,%2,%3};"
                            :"+f"(acc[mf][nf][0]),"+f"(acc[mf][nf][1]),
                             "+f"(acc[mf][nf][2]),"+f"(acc[mf][nf][3])
                            :"r"(af[PA[t]][mf][0]),"r"(af[PA[t]][mf][1]),
                             "r"(af[PA[t]][mf][2]),"r"(af[PA[t]][mf][3]),
                             "r"(bf[PB[t]][nf][0]),"r"(bf[PB[t]][nf][1]));
                    }
            }
        }
        __syncthreads();
    }

    // epilogue: direct stores + bias
#pragma unroll
    for(int mf=0;mf<2;mf++){
        int row=m0+warpM*32+mf*16+(lane>>2);
#pragma unroll
        for(int nf=0;nf<4;nf++){
            int col=n0+warpN*32+nf*8+(lane&3)*2;
            float b0v=bias[col], b1v=bias[col+1];
            float2 v0={acc[mf][nf][0]+b0v, acc[mf][nf][1]+b1v};
            float2 v1={acc[mf][nf][2]+b0v, acc[mf][nf][3]+b1v};
            *(float2*)(C+(size_t)row*ldc+col)=v0;
            *(float2*)(C+(size_t)(row+8)*ldc+col)=v1;
        }
    }
}

// ---------- prep: transpose + 3-split W[Ksrc,N] -> WT planes [N][ldwt] at col kOff ----------
__global__ __launch_bounds__(1024) void trans_split_kernel(
    const float* __restrict__ W,int N,unsigned short* __restrict__ WT,
    size_t planeStride,int ldwt,int kOff)
{
    __shared__ unsigned short s[3][32][33];
    int tx=threadIdx.x&31, ty=threadIdx.x>>5;
    int n=blockIdx.x*32+tx, k=blockIdx.y*32+ty;
    unsigned short a,b,c;
    split3(W[(size_t)k*N+n],a,b,c);
    s[0][ty][tx]=a; s[1][ty][tx]=b; s[2][ty][tx]=c;
    __syncthreads();
    int on=blockIdx.x*32+ty, ok=kOff+blockIdx.y*32+tx;
#pragma unroll
    for(int p=0;p<3;p++)
        WT[p*planeStride+(size_t)on*ldwt+ok]=s[p][tx][ty];
}

__global__ void split_rows_kernel(const float* __restrict__ src,
    unsigned short* __restrict__ dst,size_t planeStride,int n)
{
    int i=blockIdx.x*blockDim.x+threadIdx.x;
    if(i>=n) return;
    unsigned short a,b,c; split3(src[i],a,b,c);
    dst[i]=a; dst[planeStride+i]=b; dst[2*planeStride+i]=c;
}

__global__ void bias_kernel(const float* __restrict__ bi,const float* __restrict__ bh)
{ int i=blockIdx.x*blockDim.x+threadIdx.x; if(i<4*NH) g_bias[i]=bi[i]+bh[i]; }

__global__ void split_h0_kernel()
{
    int idx=blockIdx.x*blockDim.x+threadIdx.x;
    if(idx>=NB*NH) return;
    int b=idx>>9, hd=idx&(NH-1);
    unsigned short a,s1,s2; split3(g_h0[idx],a,s1,s2);
    size_t pos=(size_t)b*1024+512+hd;
    g_ehS[pos]=a; g_ehS[EHPS+pos]=s1; g_ehS[2*EHPS+pos]=s2;
}

__global__ void init_kernel(const float* __restrict__ sos)
{
    int idx=blockIdx.x*blockDim.x+threadIdx.x;
    if(idx>=NB*NE) return;
    g_c[idx]=0.f;
    int b=idx>>9, d=idx&(NE-1);
    unsigned short a,s1,s2; split3(sos[d],a,s1,s2);
    size_t pos=(size_t)b*1024+d;
    g_ehS[pos]=a; g_ehS[EHPS+pos]=s1; g_ehS[2*EHPS+pos]=s2;
}

__global__ void eos_kernel(float* __restrict__ out)
{
    int idx=blockIdx.x*blockDim.x+threadIdx.x;
    if(idx>=NB*NV) return;
    int b=idx>>11, v=idx&(NV-1);
    out[PROBS_OFF+((size_t)b*NLP+NL)*NV+v]=1.0f;
    if(v==0){
        out[SEQ_OFF+(size_t)b*NLP+NL]=0.f;
        out[LOGP_OFF+(size_t)b*NLP+NL]=0.f;
        out[ENT_OFF+(size_t)b*NLP+NL]=0.f;
    }
}

// LSTM cell: fp32 gates -> c,h; write split-h into ehS[:,512:1024]
__global__ void cell_kernel()
{
    int idx=blockIdx.x*blockDim.x+threadIdx.x;
    if(idx>=NB*NH) return;
    int b=idx>>9, hd=idx&(NH-1);
    const float* gr=g_gates+(size_t)b*(4*NH);
    float ig=1.f/(1.f+expf(-gr[hd]));
    float fg=1.f/(1.f+expf(-gr[NH+hd]));
    float gg=tanhf(gr[2*NH+hd]);
    float og=1.f/(1.f+expf(-gr[3*NH+hd]));
    float c=fg*g_c[idx]+ig*gg;
    float h=og*tanhf(c);
    g_c[idx]=c;
    unsigned short a,s1,s2; split3(h,a,s1,s2);
    size_t pos=(size_t)b*1024+512+hd;
    g_ehS[pos]=a; g_ehS[EHPS+pos]=s1; g_ehS[2*EHPS+pos]=s2;
}

// log_softmax + entropy + gumbel sample + pre-split embed gather
__global__ __launch_bounds__(256) void sampler_kernel(
    const float* __restrict__ logits,float* __restrict__ out,
    int t,unsigned int sk0,unsigned int sk1)
{
    __shared__ float row[NV];
    __shared__ float sred[256];
    __shared__ float sbest[256];
    __shared__ int sbi[256];
    __shared__ float s_max,s_lse;
    __shared__ int s_sym;
    const int b=blockIdx.x, tid=threadIdx.x;
    const float* lrow=logits+(size_t)b*NV;
    for(int v=tid;v<NV;v+=256) row[v]=lrow[v];
    __syncthreads();
    float m=-3.402823466e38f;
    for(int v=tid;v<NV;v+=256) m=fmaxf(m,row[v]);
    sred[tid]=m; __syncthreads();
    for(int s=128;s>0;s>>=1){ if(tid<s) sred[tid]=fmaxf(sred[tid],sred[tid+s]); __syncthreads(); }
    if(tid==0) s_max=sred[0];
    __syncthreads();
    const float xmax=s_max;
    float sum=0.f;
    for(int v=tid;v<NV;v+=256) sum+=expf(row[v]-xmax);
    sred[tid]=sum; __syncthreads();
    for(int s=128;s>0;s>>=1){ if(tid<s) sred[tid]+=sred[tid+s]; __syncthreads(); }
    if(tid==0) s_lse=logf(sred[0]);
    __syncthreads();
    const float lse=s_lse;
    float entacc=0.f, best=-3.402823466e38f; int besti=NV;
    float* probs_out=out+PROBS_OFF+((size_t)b*NLP+t)*NV;
    for(int v=tid;v<NV;v+=256){
        float ls=(row[v]-xmax)-lse;
        float p=expf(ls);
        probs_out[v]=p;
        entacc+=p*ls;
        unsigned int o0,o1;
        threefry2x32(sk0,sk1,0u,(unsigned int)(b*NV+v),o0,o1);
        unsigned int bits=o0^o1;
        float f=__uint_as_float((bits>>9)|0x3f800000u)-1.0f;
        float u=fmaxf(1.17549435e-38f,f+1.17549435e-38f);
        float g=-logf(-logf(u));
        float score=g+ls;
        if(score>best){best=score;besti=v;}
    }
    sred[tid]=entacc; sbest[tid]=best; sbi[tid]=besti;
    __syncthreads();
    for(int s=128;s>0;s>>=1){
        if(tid<s){
            sred[tid]+=sred[tid+s];
            float ob=sbest[tid+s]; int oi=sbi[tid+s];
            if(ob>sbest[tid]||(ob==sbest[tid]&&oi<sbi[tid])){sbest[tid]=ob;sbi[tid]=oi;}
        }
        __syncthreads();
    }
    if(tid==0){
        int sym=sbi[0]; s_sym=sym;
        out[SEQ_OFF+(size_t)b*NLP+t]=(float)sym;
        out[ENT_OFF+(size_t)b*NLP+t]=-sred[0];
        out[LOGP_OFF+(size_t)b*NLP+t]=(row[sym]-xmax)-lse;
    }
    __syncthreads();
    const int sym=s_sym;
    for(int i=tid;i<NE;i+=256){
        size_t dpos=(size_t)b*1024+i, spos=(size_t)sym*512+i;
        g_ehS[dpos]=g_embS[spos];
        g_ehS[EHPS+dpos]=g_embS[EPS+spos];
        g_ehS[2*EHPS+dpos]=g_embS[2*EPS+spos];
    }
}

// ---------------- launch ----------------
extern "C" void kernel_launch(void* const* d_in,const int* in_sizes,int n_in,
                              void* d_out,int out_size)
{
    (void)in_sizes;(void)n_in;(void)out_size;
    const float* x        =(const float*)d_in[0];
    const float* agent_w  =(const float*)d_in[1];
    const float* agent_b  =(const float*)d_in[2];
    const float* sos      =(const float*)d_in[3];
    const float* embedding=(const float*)d_in[4];
    const float* w_ih     =(const float*)d_in[5];
    const float* w_hh     =(const float*)d_in[6];
    const float* b_ih     =(const float*)d_in[7];
    const float* b_hh     =(const float*)d_in[8];
    const float* out_w    =(const float*)d_in[9];
    const float* out_b    =(const float*)d_in[10];
    float* out=(float*)d_out;

    static int smem_set=0;
    if(!smem_set){
        cudaFuncSetAttribute(gemm_mma,cudaFuncAttributeMaxDynamicSharedMemorySize,GSMEM);
        smem_set=1;
    }

    unsigned short *pgw,*pow,*paw,*pxs,*peh,*pes;
    float *pb,*ph0,*pg,*pl;
    cudaGetSymbolAddress((void**)&pgw,g_gatesWT);
    cudaGetSymbolAddress((void**)&pow,g_outWT);
    cudaGetSymbolAddress((void**)&paw,g_agentWT);
    cudaGetSymbolAddress((void**)&pxs,g_xS);
    cudaGetSymbolAddress((void**)&peh,g_ehS);
    cudaGetSymbolAddress((void**)&pes,g_embS);
    cudaGetSymbolAddress((void**)&pb,g_bias);
    cudaGetSymbolAddress((void**)&ph0,g_h0);
    cudaGetSymbolAddress((void**)&pg,g_gates);
    cudaGetSymbolAddress((void**)&pl,g_logits);

    // host-side JAX key chain: key(1)=(0,1); fold-like split per step
    unsigned int key0=0u,key1=1u,sk0[NL],sk1[NL];
    for(int t=0;t<NL;t++){
        unsigned int n0,n1,s0,s1;
        threefry2x32(key0,key1,0u,0u,n0,n1);
        threefry2x32(key0,key1,0u,1u,s0,s1);
        sk0[t]=s0; sk1[t]=s1; key0=n0; key1=n1;
    }

    // prep: weight transposes + splits (per launch, deterministic)
    trans_split_kernel<<<dim3(NV/32,NE/32),1024>>>(w_ih,NV,pgw,GPS,1024,0);
    trans_split_kernel<<<dim3(NV/32,NH/32),1024>>>(w_hh,NV,pgw,GPS,1024,512);
    trans_split_kernel<<<dim3(NV/32,NH/32),1024>>>(out_w,NV,pow,OPS,512,0);
    trans_split_kernel<<<dim3(NH/32,NIN/32),1024>>>(agent_w,NH,paw,APS,1024,0);
    split_rows_kernel<<<(NB*NIN+255)/256,256>>>(x,pxs,XPS,NB*NIN);
    split_rows_kernel<<<(NV*NE+255)/256,256>>>(embedding,pes,EPS,NV*NE);
    bias_kernel<<<(4*NH+255)/256,256>>>(b_ih,b_hh);
    init_kernel<<<(NB*NE+255)/256,256>>>(sos);
    eos_kernel<<<(NB*NV+255)/256,256>>>(out);

    // h0 = x @ agent_w + agent_b  [512,512], K=1024
    gemm_mma<<<dim3(NH/128,NB/64),256,GSMEM>>>(
        pxs,pxs+XPS,pxs+2*XPS,NIN, paw,paw+APS,paw+2*APS,1024,
        NIN,ph0,NH,agent_b);
    split_h0_kernel<<<(NB*NH+255)/256,256>>>();

    for(int t=0;t<NL;t++){
        // gates = [e|h] @ [w_ih;w_hh]^T + bias -> [512,2048], K=1024
        gemm_mma<<<dim3(4*NH/128,NB/64),256,GSMEM>>>(
            peh,peh+EHPS,peh+2*EHPS,1024, pgw,pgw+GPS,pgw+2*GPS,1024,
            1024,pg,4*NH,pb);
        cell_kernel<<<(NB*NH+255)/256,256>>>();
        // logits = h @ out_w^T + out_b -> [512,2048], K=512
        gemm_mma<<<dim3(NV/128,NB/64),256,GSMEM>>>(
            peh+512,peh+EHPS+512,peh+2*EHPS+512,1024, pow,pow+OPS,pow+2*OPS,512,
            512,pl,NV,out_b);
        sampler_kernel<<<NB,256>>>(pl,out,t,sk0[t],sk1[t]);
    }
}

// round 12
// speedup vs baseline: 2.6913x; 1.0054x over previous
#include <cuda_runtime.h>
#include <cuda_bf16.h>
#include <cstdint>

constexpr int NB=512, NH=512, NE=512, NV=2048, NIN=1024, NL=32, NLP=33;
constexpr size_t SEQ_OFF=0;
constexpr size_t PROBS_OFF=(size_t)NB*NLP;
constexpr size_t LOGP_OFF=PROBS_OFF+(size_t)NB*NLP*NV;
constexpr size_t ENT_OFF=LOGP_OFF+(size_t)NB*NLP;

// plane strides (elements)
constexpr size_t GPS=(size_t)NV*1024;   // gatesWT [2048][1024]
constexpr size_t OPS=(size_t)NV*512;    // outWT   [2048][512]
constexpr size_t APS=(size_t)NH*1024;   // agentWT [512][1024]
constexpr size_t XPS=(size_t)NB*NIN;    // xS      [512][1024]
constexpr size_t EHPS=(size_t)NB*1024;  // ehS     [512][1024] = [e|h]
constexpr size_t EPS=(size_t)NV*NE;     // embS    [2048][512]

__device__ __align__(16) unsigned short g_gatesWT[3*GPS];
__device__ __align__(16) unsigned short g_outWT[3*OPS];
__device__ __align__(16) unsigned short g_agentWT[3*APS];
__device__ __align__(16) unsigned short g_xS[3*XPS];
__device__ __align__(16) unsigned short g_ehS[3*EHPS];
__device__ __align__(16) unsigned short g_embS[3*EPS];
__device__ float g_bias[4*NH];
__device__ float g_c[NB*NH];
__device__ float g_logits[NB*NV];

__device__ __forceinline__ void split3(float v, unsigned short& o0,
                                       unsigned short& o1, unsigned short& o2)
{
    __nv_bfloat16 b0=__float2bfloat16_rn(v);
    float r=v-__bfloat162float(b0);
    __nv_bfloat16 b1=__float2bfloat16_rn(r);
    float r2=r-__bfloat162float(b1);
    __nv_bfloat16 b2=__float2bfloat16_rn(r2);
    o0=__bfloat16_as_ushort(b0); o1=__bfloat16_as_ushort(b1); o2=__bfloat16_as_ushort(b2);
}

// ---------- threefry2x32 (JAX-exact, verified) ----------
#define TF_ROTL(x,d) (((x)<<(d))|((x)>>(32-(d))))
#define TF_ROUND(r) { x0+=x1; x1=TF_ROTL(x1,r); x1^=x0; }
__host__ __device__ __forceinline__ void threefry2x32(
    unsigned int k0,unsigned int k1,unsigned int x0,unsigned int x1,
    unsigned int& o0,unsigned int& o1)
{
    unsigned int ks0=k0,ks1=k1,ks2=k0^k1^0x1BD11BDAu;
    x0+=ks0; x1+=ks1;
    TF_ROUND(13) TF_ROUND(15) TF_ROUND(26) TF_ROUND(6)
    x0+=ks1; x1+=ks2+1u;
    TF_ROUND(17) TF_ROUND(29) TF_ROUND(16) TF_ROUND(24)
    x0+=ks2; x1+=ks0+2u;
    TF_ROUND(13) TF_ROUND(15) TF_ROUND(26) TF_ROUND(6)
    x0+=ks0; x1+=ks1+3u;
    TF_ROUND(17) TF_ROUND(29) TF_ROUND(16) TF_ROUND(24)
    x0+=ks1; x1+=ks2+4u;
    TF_ROUND(13) TF_ROUND(15) TF_ROUND(26) TF_ROUND(6)
    x0+=ks2; x1+=ks0+5u;
    o0=x0; o1=x1;
}

__device__ __forceinline__ uint32_t smem_u32(const void* p)
{ uint32_t a; asm("{ .reg .u64 t; cvta.to.shared.u64 t, %1; cvt.u32.u64 %0, t; }":"=r"(a):"l"(p)); return a; }

__device__ __forceinline__ uint32_t sw128(uint32_t off)
{ return off ^ ((off >> 3) & 0x70u); }

// ---------- portable tensor-core bf16x3 GEMM (mma.sync, sm_80+ ISA) ----------
// C[M,N] fp32 = sum_{6 split products} A[M,K] * B[N,K]^T (+ bias)
// Block tile 64(M) x 128(N), 8 warps (2x4), warp tile 32x32, K staged 64-wide.
// MODE 0: plain store C + bias (logits)
// MODE 1: gate-interleaved N mapping (n = gate*512 + bx*32 + j) + fused LSTM cell:
//         epilogue computes c,h and writes split-h into ehOut; no C write.
// MODE 2: h0: epilogue writes split3(acc+bias) into ehOut h-half; no C write.
constexpr int APL   = 64*64*2;            // 8192 B per A plane tile
constexpr int BPL   = 128*64*2;           // 16384 B per B plane tile
constexpr int STAGE = 3*APL + 3*BPL;      // 73728 B
constexpr int GSMEM = 2*STAGE;            // 147456 B

template<int MODE>
__global__ __launch_bounds__(256) void gemm_mma(
    const unsigned short* __restrict__ a0,const unsigned short* __restrict__ a1,
    const unsigned short* __restrict__ a2,int lda,
    const unsigned short* __restrict__ b0,const unsigned short* __restrict__ b1,
    const unsigned short* __restrict__ b2,int ldb,
    int K,float* __restrict__ C,int ldc,const float* __restrict__ bias,
    float* __restrict__ cState,unsigned short* __restrict__ ehOut)
{
    extern __shared__ char sm[];
    const int tid=threadIdx.x, wid=tid>>5, lane=tid&31;
    const int bx=blockIdx.x;
    const int m0=blockIdx.y*64, n0=bx*128;
    const int warpM=wid&1, warpN=wid>>1;
    const uint32_t sbase=smem_u32(sm);
    const unsigned short* Ap[3]={a0,a1,a2};
    const unsigned short* Bp[3]={b0,b1,b2};
    const int KT=K>>6;

    float acc[2][4][4];
#pragma unroll
    for(int i=0;i<2;i++)
#pragma unroll
        for(int j=0;j<4;j++)
#pragma unroll
            for(int k=0;k<4;k++) acc[i][j][k]=0.f;

    // ldmatrix lane-address components (within-tile)
    const int aRow = warpM*32 + (lane&7) + ((lane>>3)&1)*8;   // + mf*16
    const int aColL = ((lane>>4)&1)*8;                        // + kk*16
    const int bRow4 = warpN*32 + ((lane>>4)&1)*8 + (lane&7);  // + nfb*8
    const int bColL4 = ((lane>>3)&1)*8;                       // + kk*16

    // ---- cp.async stage issue ----
    auto issue=[&](int kt,int buf){
        uint32_t st=sbase+(uint32_t)buf*STAGE;
#pragma unroll
        for(int i=0;i<6;i++){          // A planes: 3 x 512 16B-chunks
            int idx=tid+i*256;
            int p=idx>>9, rem=idx&511, r=rem>>3, c8=rem&7;
            const unsigned short* g=Ap[p]+(size_t)(m0+r)*lda+kt*64+c8*8;
            uint32_t so=(uint32_t)p*APL + sw128((uint32_t)r*128+(uint32_t)c8*16);
            asm volatile("cp.async.cg.shared.global [%0],[%1],16;\n"
                         ::"r"(st+so),"l"(g));
        }
#pragma unroll
        for(int i=0;i<12;i++){         // B planes: 3 x 1024 16B-chunks
            int j=tid+i*256;
            int p=j>>10, rem=j&1023, r=rem>>3, c8=rem&7;
            int srcN = (MODE==1) ? (((r>>5)<<9) + bx*32 + (r&31)) : (n0 + r);
            const unsigned short* g=Bp[p]+(size_t)srcN*ldb+kt*64+c8*8;
            uint32_t so=(uint32_t)(3*APL)+(uint32_t)p*BPL + sw128((uint32_t)r*128+(uint32_t)c8*16);
            asm volatile("cp.async.cg.shared.global [%0],[%1],16;\n"
                         ::"r"(st+so),"l"(g));
        }
        asm volatile("cp.async.commit_group;\n":::"memory");
    };

    issue(0,0);

#pragma unroll 1
    for(int kt=0;kt<KT;kt++){
        if(kt+1<KT){
            issue(kt+1,(kt+1)&1);
            asm volatile("cp.async.wait_group 1;\n":::"memory");
        }else{
            asm volatile("cp.async.wait_group 0;\n":::"memory");
        }
        __syncthreads();

        const uint32_t st=sbase+(uint32_t)(kt&1)*STAGE;
#pragma unroll
        for(int kk=0;kk<4;kk++){
            uint32_t af[3][2][4], bf[3][4][2];
#pragma unroll
            for(int p=0;p<3;p++){
#pragma unroll
                for(int mf=0;mf<2;mf++){
                    uint32_t addr=st+(uint32_t)p*APL+
                        sw128((uint32_t)(aRow+mf*16)*128+(uint32_t)(kk*16+aColL)*2);
                    asm volatile("ldmatrix.sync.aligned.m8n8.x4.shared.b16 {%0,%1,%2,%3},[%4];"
                        :"=r"(af[p][mf][0]),"=r"(af[p][mf][1]),
                         "=r"(af[p][mf][2]),"=r"(af[p][mf][3]):"r"(addr));
                }
#pragma unroll
                for(int nfb=0;nfb<4;nfb+=2){
                    uint32_t addr=st+(uint32_t)(3*APL)+(uint32_t)p*BPL+
                        sw128((uint32_t)(bRow4+nfb*8)*128+(uint32_t)(kk*16+bColL4)*2);
                    asm volatile("ldmatrix.sync.aligned.m8n8.x4.shared.b16 {%0,%1,%2,%3},[%4];"
                        :"=r"(bf[p][nfb][0]),"=r"(bf[p][nfb][1]),
                         "=r"(bf[p][nfb+1][0]),"=r"(bf[p][nfb+1][1]):"r"(addr));
                }
            }
            const int PA[6]={0,0,1,1,0,2};
            const int PB[6]={0,1,0,1,2,0};
#pragma unroll
            for(int t=0;t<6;t++){
#pragma unroll
                for(int mf=0;mf<2;mf++)
#pragma unroll
                    for(int nf=0;nf<4;nf++){
                        asm volatile(
                            "mma.sync.aligned.m16n8k16.row.col.f32.bf16.bf16.f32 "
                            "{%0,%1,%2,%3},{%4,%5,%6,%7},{%8,%9},{%0,%1,%2,%3};"
                            :"+f"(acc[mf][nf][0]),"+f"(acc[mf][nf][1]),
                             "+f"(acc[mf][nf][2]),"+f"(acc[mf][nf][3])
                            :"r"(af[PA[t]][mf][0]),"r"(af[PA[t]][mf][1]),
                             "r"(af[PA[t]][mf][2]),"r"(af[PA[t]][mf][3]),
                             "r"(bf[PB[t]][nf][0]),"r"(bf[PB[t]][nf][1]));
                    }
            }
        }
        __syncthreads();
    }

    if(MODE==0){
        // plain: direct stores + bias
#pragma unroll
        for(int mf=0;mf<2;mf++){
            int row=m0+warpM*32+mf*16+(lane>>2);
#pragma unroll
            for(int nf=0;nf<4;nf++){
                int col=n0+warpN*32+nf*8+(lane&3)*2;
                float b0v=bias[col], b1v=bias[col+1];
                float2 v0={acc[mf][nf][0]+b0v, acc[mf][nf][1]+b1v};
                float2 v1={acc[mf][nf][2]+b0v, acc[mf][nf][3]+b1v};
                *(float2*)(C+(size_t)row*ldc+col)=v0;
                *(float2*)(C+(size_t)(row+8)*ldc+col)=v1;
            }
        }
    }else if(MODE==2){
        // h0: split3(acc+bias) -> ehOut h-half
#pragma unroll
        for(int mf=0;mf<2;mf++){
            int row=warpM*32+mf*16+(lane>>2);
#pragma unroll
            for(int nf=0;nf<4;nf++){
                int col=n0+warpN*32+nf*8+(lane&3)*2;
                float b0v=bias[col], b1v=bias[col+1];
                float vals[4]={acc[mf][nf][0]+b0v, acc[mf][nf][1]+b1v,
                               acc[mf][nf][2]+b0v, acc[mf][nf][3]+b1v};
#pragma unroll
                for(int q=0;q<4;q++){
                    int rr=m0+row+(q>>1)*8, cc=col+(q&1);
                    unsigned short s0,s1,s2; split3(vals[q],s0,s1,s2);
                    size_t pos=(size_t)rr*1024+512+cc;
                    ehOut[pos]=s0; ehOut[EHPS+pos]=s1; ehOut[2*EHPS+pos]=s2;
                }
            }
        }
    }else{
        // MODE 1: gates -> smem -> fused LSTM cell
        float* gs=(float*)sm;              // [64][132]
        constexpr int P=132;
#pragma unroll
        for(int mf=0;mf<2;mf++){
            int row=warpM*32+mf*16+(lane>>2);
#pragma unroll
            for(int nf=0;nf<4;nf++){
                int col=warpN*32+nf*8+(lane&3)*2;
                gs[row*P+col]  =acc[mf][nf][0];
                gs[row*P+col+1]=acc[mf][nf][1];
                gs[(row+8)*P+col]  =acc[mf][nf][2];
                gs[(row+8)*P+col+1]=acc[mf][nf][3];
            }
        }
        __syncthreads();
#pragma unroll
        for(int i=0;i<8;i++){
            int idx=tid+i*256;             // 2048 = 64 rows x 32 hd
            int row=idx>>5, hd=idx&31;
            int hdg=bx*32+hd;
            int b=m0+row;
            float ig=gs[row*P+hd]    +bias[hdg];
            float fg=gs[row*P+32+hd] +bias[512+hdg];
            float gg=gs[row*P+64+hd] +bias[1024+hdg];
            float og=gs[row*P+96+hd] +bias[1536+hdg];
            ig=1.f/(1.f+expf(-ig));
            fg=1.f/(1.f+expf(-fg));
            gg=tanhf(gg);
            og=1.f/(1.f+expf(-og));
            size_t ci=(size_t)b*512+hdg;
            float c=fg*cState[ci]+ig*gg;
            float h=og*tanhf(c);
            cState[ci]=c;
            unsigned short s0,s1,s2; split3(h,s0,s1,s2);
            size_t pos=(size_t)b*1024+512+hdg;
            ehOut[pos]=s0; ehOut[EHPS+pos]=s1; ehOut[2*EHPS+pos]=s2;
        }
    }
}

// ---------- prep: transpose + 3-split W[Ksrc,N] -> WT planes [N][ldwt] at col kOff ----------
__global__ __launch_bounds__(1024) void trans_split_kernel(
    const float* __restrict__ W,int N,unsigned short* __restrict__ WT,
    size_t planeStride,int ldwt,int kOff)
{
    __shared__ unsigned short s[3][32][33];
    int tx=threadIdx.x&31, ty=threadIdx.x>>5;
    int n=blockIdx.x*32+tx, k=blockIdx.y*32+ty;
    unsigned short a,b,c;
    split3(W[(size_t)k*N+n],a,b,c);
    s[0][ty][tx]=a; s[1][ty][tx]=b; s[2][ty][tx]=c;
    __syncthreads();
    int on=blockIdx.x*32+ty, ok=kOff+blockIdx.y*32+tx;
#pragma unroll
    for(int p=0;p<3;p++)
        WT[p*planeStride+(size_t)on*ldwt+ok]=s[p][tx][ty];
}

__global__ void split_rows_kernel(const float* __restrict__ src,
    unsigned short* __restrict__ dst,size_t planeStride,int n)
{
    int i=blockIdx.x*blockDim.x+threadIdx.x;
    if(i>=n) return;
    unsigned short a,b,c; split3(src[i],a,b,c);
    dst[i]=a; dst[planeStride+i]=b; dst[2*planeStride+i]=c;
}

__global__ void bias_kernel(const float* __restrict__ bi,const float* __restrict__ bh)
{ int i=blockIdx.x*blockDim.x+threadIdx.x; if(i<4*NH) g_bias[i]=bi[i]+bh[i]; }

__global__ void init_kernel(const float* __restrict__ sos)
{
    int idx=blockIdx.x*blockDim.x+threadIdx.x;
    if(idx>=NB*NE) return;
    g_c[idx]=0.f;
    int b=idx>>9, d=idx&(NE-1);
    unsigned short a,s1,s2; split3(sos[d],a,s1,s2);
    size_t pos=(size_t)b*1024+d;
    g_ehS[pos]=a; g_ehS[EHPS+pos]=s1; g_ehS[2*EHPS+pos]=s2;
}

__global__ void eos_kernel(float* __restrict__ out)
{
    int idx=blockIdx.x*blockDim.x+threadIdx.x;
    if(idx>=NB*NV) return;
    int b=idx>>11, v=idx&(NV-1);
    out[PROBS_OFF+((size_t)b*NLP+NL)*NV+v]=1.0f;
    if(v==0){
        out[SEQ_OFF+(size_t)b*NLP+NL]=0.f;
        out[LOGP_OFF+(size_t)b*NLP+NL]=0.f;
        out[ENT_OFF+(size_t)b*NLP+NL]=0.f;
    }
}

// log_softmax + entropy + gumbel sample + pre-split embed gather
__global__ __launch_bounds__(256) void sampler_kernel(
    const float* __restrict__ logits,float* __restrict__ out,
    int t,unsigned int sk0,unsigned int sk1)
{
    __shared__ float row[NV];
    __shared__ float sred[256];
    __shared__ float sbest[256];
    __shared__ int sbi[256];
    __shared__ float s_max,s_lse;
    __shared__ int s_sym;
    const int b=blockIdx.x, tid=threadIdx.x;
    const float* lrow=logits+(size_t)b*NV;
    for(int v=tid;v<NV;v+=256) row[v]=lrow[v];
    __syncthreads();
    float m=-3.402823466e38f;
    for(int v=tid;v<NV;v+=256) m=fmaxf(m,row[v]);
    sred[tid]=m; __syncthreads();
    for(int s=128;s>0;s>>=1){ if(tid<s) sred[tid]=fmaxf(sred[tid],sred[tid+s]); __syncthreads(); }
    if(tid==0) s_max=sred[0];
    __syncthreads();
    const float xmax=s_max;
    float sum=0.f;
    for(int v=tid;v<NV;v+=256) sum+=expf(row[v]-xmax);
    sred[tid]=sum; __syncthreads();
    for(int s=128;s>0;s>>=1){ if(tid<s) sred[tid]+=sred[tid+s]; __syncthreads(); }
    if(tid==0) s_lse=logf(sred[0]);
    __syncthreads();
    const float lse=s_lse;
    float entacc=0.f, best=-3.402823466e38f; int besti=NV;
    float* probs_out=out+PROBS_OFF+((size_t)b*NLP+t)*NV;
    for(int v=tid;v<NV;v+=256){
        float ls=(row[v]-xmax)-lse;
        float p=expf(ls);
        probs_out[v]=p;
        entacc+=p*ls;
        unsigned int o0,o1;
        threefry2x32(sk0,sk1,0u,(unsigned int)(b*NV+v),o0,o1);
        unsigned int bits=o0^o1;
        float f=__uint_as_float((bits>>9)|0x3f800000u)-1.0f;
        float u=fmaxf(1.17549435e-38f,f+1.17549435e-38f);
        float g=-logf(-logf(u));
        float score=g+ls;
        if(score>best){best=score;besti=v;}
    }
    sred[tid]=entacc; sbest[tid]=best; sbi[tid]=besti;
    __syncthreads();
    for(int s=128;s>0;s>>=1){
        if(tid<s){
            sred[tid]+=sred[tid+s];
            float ob=sbest[tid+s]; int oi=sbi[tid+s];
            if(ob>sbest[tid]||(ob==sbest[tid]&&oi<sbi[tid])){sbest[tid]=ob;sbi[tid]=oi;}
        }
        __syncthreads();
    }
    if(tid==0){
        int sym=sbi[0]; s_sym=sym;
        out[SEQ_OFF+(size_t)b*NLP+t]=(float)sym;
        out[ENT_OFF+(size_t)b*NLP+t]=-sred[0];
        out[LOGP_OFF+(size_t)b*NLP+t]=(row[sym]-xmax)-lse;
    }
    __syncthreads();
    const int sym=s_sym;
    for(int i=tid;i<NE;i+=256){
        size_t dpos=(size_t)b*1024+i, spos=(size_t)sym*512+i;
        g_ehS[dpos]=g_embS[spos];
        g_ehS[EHPS+dpos]=g_embS[EPS+spos];
        g_ehS[2*EHPS+dpos]=g_embS[2*EPS+spos];
    }
}

// ---------------- launch ----------------
extern "C" void kernel_launch(void* const* d_in,const int* in_sizes,int n_in,
                              void* d_out,int out_size)
{
    (void)in_sizes;(void)n_in;(void)out_size;
    const float* x        =(const float*)d_in[0];
    const float* agent_w  =(const float*)d_in[1];
    const float* agent_b  =(const float*)d_in[2];
    const float* sos      =(const float*)d_in[3];
    const float* embedding=(const float*)d_in[4];
    const float* w_ih     =(const float*)d_in[5];
    const float* w_hh     =(const float*)d_in[6];
    const float* b_ih     =(const float*)d_in[7];
    const float* b_hh     =(const float*)d_in[8];
    const float* out_w    =(const float*)d_in[9];
    const float* out_b    =(const float*)d_in[10];
    float* out=(float*)d_out;

    cudaFuncSetAttribute(gemm_mma<0>,cudaFuncAttributeMaxDynamicSharedMemorySize,GSMEM);
    cudaFuncSetAttribute(gemm_mma<1>,cudaFuncAttributeMaxDynamicSharedMemorySize,GSMEM);
    cudaFuncSetAttribute(gemm_mma<2>,cudaFuncAttributeMaxDynamicSharedMemorySize,GSMEM);

    unsigned short *pgw,*pow,*paw,*pxs,*peh,*pes;
    float *pb,*pc,*pl;
    cudaGetSymbolAddress((void**)&pgw,g_gatesWT);
    cudaGetSymbolAddress((void**)&pow,g_outWT);
    cudaGetSymbolAddress((void**)&paw,g_agentWT);
    cudaGetSymbolAddress((void**)&pxs,g_xS);
    cudaGetSymbolAddress((void**)&peh,g_ehS);
    cudaGetSymbolAddress((void**)&pes,g_embS);
    cudaGetSymbolAddress((void**)&pb,g_bias);
    cudaGetSymbolAddress((void**)&pc,g_c);
    cudaGetSymbolAddress((void**)&pl,g_logits);

    // host-side JAX key chain: key(1)=(0,1); fold-like split per step
    unsigned int key0=0u,key1=1u,sk0[NL],sk1[NL];
    for(int t=0;t<NL;t++){
        unsigned int n0,n1,s0,s1;
        threefry2x32(key0,key1,0u,0u,n0,n1);
        threefry2x32(key0,key1,0u,1u,s0,s1);
        sk0[t]=s0; sk1[t]=s1; key0=n0; key1=n1;
    }

    // prep: weight transposes + splits (per launch, deterministic)
    trans_split_kernel<<<dim3(NV/32,NE/32),1024>>>(w_ih,NV,pgw,GPS,1024,0);
    trans_split_kernel<<<dim3(NV/32,NH/32),1024>>>(w_hh,NV,pgw,GPS,1024,512);
    trans_split_kernel<<<dim3(NV/32,NH/32),1024>>>(out_w,NV,pow,OPS,512,0);
    trans_split_kernel<<<dim3(NH/32,NIN/32),1024>>>(agent_w,NH,paw,APS,1024,0);
    split_rows_kernel<<<(NB*NIN+255)/256,256>>>(x,pxs,XPS,NB*NIN);
    split_rows_kernel<<<(NV*NE+255)/256,256>>>(embedding,pes,EPS,NV*NE);
    bias_kernel<<<(4*NH+255)/256,256>>>(b_ih,b_hh);
    init_kernel<<<(NB*NE+255)/256,256>>>(sos);
    eos_kernel<<<(NB*NV+255)/256,256>>>(out);

    // h0 = x @ agent_w + agent_b -> split directly into ehS h-half  [512,512], K=1024
    gemm_mma<2><<<dim3(NH/128,NB/64),256,GSMEM>>>(
        pxs,pxs+XPS,pxs+2*XPS,NIN, paw,paw+APS,paw+2*APS,1024,
        NIN,nullptr,0,agent_b,nullptr,peh);

    for(int t=0;t<NL;t++){
        // gates GEMM + fused LSTM cell: [e|h] @ [w_ih;w_hh]^T + bias, K=1024
        gemm_mma<1><<<dim3(16,NB/64),256,GSMEM>>>(
            peh,peh+EHPS,peh+2*EHPS,1024, pgw,pgw+GPS,pgw+2*GPS,1024,
            1024,nullptr,0,pb,pc,peh);
        // logits = h @ out_w^T + out_b -> [512,2048], K=512
        gemm_mma<0><<<dim3(NV/128,NB/64),256,GSMEM>>>(
            peh+512,peh+EHPS+512,peh+2*EHPS+512,1024, pow,pow+OPS,pow+2*OPS,512,
            512,pl,NV,out_b,nullptr,nullptr);
        sampler_kernel<<<NB,256>>>(pl,out,t,sk0[t],sk1[t]);
    }
}

// round 16
// speedup vs baseline: 2.7166x; 1.0094x over previous
#include <cuda_runtime.h>
#include <cuda_bf16.h>
#include <cstdint>

constexpr int NB=512, NH=512, NE=512, NV=2048, NIN=1024, NL=32, NLP=33;
constexpr size_t SEQ_OFF=0;
constexpr size_t PROBS_OFF=(size_t)NB*NLP;
constexpr size_t LOGP_OFF=PROBS_OFF+(size_t)NB*NLP*NV;
constexpr size_t ENT_OFF=LOGP_OFF+(size_t)NB*NLP;

// plane strides (elements)
constexpr size_t GPS=(size_t)NV*1024;   // gatesWT [2048][1024]
constexpr size_t OPS=(size_t)NV*512;    // outWT   [2048][512]
constexpr size_t APS=(size_t)NH*1024;   // agentWT [512][1024]
constexpr size_t XPS=(size_t)NB*NIN;    // xS      [512][1024]
constexpr size_t EHPS=(size_t)NB*1024;  // eh      [512][1024] = [e|h]
constexpr size_t EPS=(size_t)NV*NE;     // embS    [2048][512]

__device__ __align__(16) unsigned short g_gatesWT[3*GPS];
__device__ __align__(16) unsigned short g_outWT[3*OPS];
__device__ __align__(16) unsigned short g_agentWT[3*APS];
__device__ __align__(16) unsigned short g_xS[3*XPS];
__device__ __align__(16) unsigned short g_ehA[3*EHPS];   // ping
__device__ __align__(16) unsigned short g_ehB[3*EHPS];   // pong
__device__ __align__(16) unsigned short g_embS[3*EPS];
__device__ float g_bias[4*NH];
__device__ float g_c[NB*NH];
__device__ float g_logits[NB*NV];

__device__ __forceinline__ void split3(float v, unsigned short& o0,
                                       unsigned short& o1, unsigned short& o2)
{
    __nv_bfloat16 b0=__float2bfloat16_rn(v);
    float r=v-__bfloat162float(b0);
    __nv_bfloat16 b1=__float2bfloat16_rn(r);
    float r2=r-__bfloat162float(b1);
    __nv_bfloat16 b2=__float2bfloat16_rn(r2);
    o0=__bfloat16_as_ushort(b0); o1=__bfloat16_as_ushort(b1); o2=__bfloat16_as_ushort(b2);
}

// ---------- threefry2x32 (JAX-exact, verified) ----------
#define TF_ROTL(x,d) (((x)<<(d))|((x)>>(32-(d))))
#define TF_ROUND(r) { x0+=x1; x1=TF_ROTL(x1,r); x1^=x0; }
__host__ __device__ __forceinline__ void threefry2x32(
    unsigned int k0,unsigned int k1,unsigned int x0,unsigned int x1,
    unsigned int& o0,unsigned int& o1)
{
    unsigned int ks0=k0,ks1=k1,ks2=k0^k1^0x1BD11BDAu;
    x0+=ks0; x1+=ks1;
    TF_ROUND(13) TF_ROUND(15) TF_ROUND(26) TF_ROUND(6)
    x0+=ks1; x1+=ks2+1u;
    TF_ROUND(17) TF_ROUND(29) TF_ROUND(16) TF_ROUND(24)
    x0+=ks2; x1+=ks0+2u;
    TF_ROUND(13) TF_ROUND(15) TF_ROUND(26) TF_ROUND(6)
    x0+=ks0; x1+=ks1+3u;
    TF_ROUND(17) TF_ROUND(29) TF_ROUND(16) TF_ROUND(24)
    x0+=ks1; x1+=ks2+4u;
    TF_ROUND(13) TF_ROUND(15) TF_ROUND(26) TF_ROUND(6)
    x0+=ks2; x1+=ks0+5u;
    o0=x0; o1=x1;
}

__device__ __forceinline__ uint32_t smem_u32(const void* p)
{ uint32_t a; asm("{ .reg .u64 t; cvta.to.shared.u64 t, %1; cvt.u32.u64 %0, t; }":"=r"(a):"l"(p)); return a; }

__device__ __forceinline__ uint32_t sw128(uint32_t off)
{ return off ^ ((off >> 3) & 0x70u); }

// ---------- portable tensor-core bf16x3 GEMM (mma.sync, sm_80+ ISA) ----------
// C[M,N] fp32 = sum_{6 split products} A[M,K] * B[N,K]^T (+ bias)
// Block tile 64(M) x 64(N), 8 warps (4Mx2N), warp tile 16x32, K staged 64-wide.
// 2 blocks/SM (96KB smem) so barrier stalls are covered.
// MODE 0: plain store C + bias (logits)
// MODE 1: gate-interleaved N mapping (n = gate*512 + bx*16 + j) + fused LSTM cell
//         (reads A from ehIn ping buffer, writes split-h to ehOut pong buffer)
// MODE 2: h0: epilogue writes split3(acc+bias) into ehOut h-half
constexpr int APL   = 64*64*2;            // 8192 B per A plane tile
constexpr int BPL   = 64*64*2;            // 8192 B per B plane tile
constexpr int STAGE = 3*APL + 3*BPL;      // 49152 B
constexpr int GSMEM = 2*STAGE;            // 98304 B

template<int MODE>
__global__ __launch_bounds__(256,2) void gemm_mma(
    const unsigned short* __restrict__ a0,const unsigned short* __restrict__ a1,
    const unsigned short* __restrict__ a2,int lda,
    const unsigned short* __restrict__ b0,const unsigned short* __restrict__ b1,
    const unsigned short* __restrict__ b2,int ldb,
    int K,float* __restrict__ C,int ldc,const float* __restrict__ bias,
    float* __restrict__ cState,unsigned short* __restrict__ ehOut)
{
    extern __shared__ char sm[];
    const int tid=threadIdx.x, wid=tid>>5, lane=tid&31;
    const int bx=blockIdx.x;
    const int m0=blockIdx.y*64, n0=bx*64;
    const int warpM=wid&3, warpN=wid>>2;       // 4 x 2 warps
    const uint32_t sbase=smem_u32(sm);
    const unsigned short* Ap[3]={a0,a1,a2};
    const unsigned short* Bp[3]={b0,b1,b2};
    const int KT=K>>6;

    float acc[4][4];                            // nf x 4 (warp tile 16x32)
#pragma unroll
    for(int j=0;j<4;j++)
#pragma unroll
        for(int k=0;k<4;k++) acc[j][k]=0.f;

    // ldmatrix lane-address components (within-tile)
    const int aRow = warpM*16 + (lane&7) + ((lane>>3)&1)*8;
    const int aColL = ((lane>>4)&1)*8;                        // + kk*16
    const int bRow4 = warpN*32 + ((lane>>4)&1)*8 + (lane&7);  // + nfb*8
    const int bColL4 = ((lane>>3)&1)*8;                       // + kk*16

    // ---- cp.async stage issue ----
    auto issue=[&](int kt,int buf){
        uint32_t st=sbase+(uint32_t)buf*STAGE;
#pragma unroll
        for(int i=0;i<6;i++){          // A planes: 3 x 512 chunks
            int idx=tid+i*256;
            int p=idx>>9, rem=idx&511, r=rem>>3, c8=rem&7;
            const unsigned short* g=Ap[p]+(size_t)(m0+r)*lda+kt*64+c8*8;
            uint32_t so=(uint32_t)p*APL + sw128((uint32_t)r*128+(uint32_t)c8*16);
            asm volatile("cp.async.cg.shared.global [%0],[%1],16;\n"
                         ::"r"(st+so),"l"(g));
        }
#pragma unroll
        for(int i=0;i<6;i++){          // B planes: 3 x 512 chunks
            int idx=tid+i*256;
            int p=idx>>9, rem=idx&511, r=rem>>3, c8=rem&7;
            int srcN = (MODE==1) ? (((r>>4)<<9) + bx*16 + (r&15)) : (n0 + r);
            const unsigned short* g=Bp[p]+(size_t)srcN*ldb+kt*64+c8*8;
            uint32_t so=(uint32_t)(3*APL)+(uint32_t)p*BPL + sw128((uint32_t)r*128+(uint32_t)c8*16);
            asm volatile("cp.async.cg.shared.global [%0],[%1],16;\n"
                         ::"r"(st+so),"l"(g));
        }
        asm volatile("cp.async.commit_group;\n":::"memory");
    };

    issue(0,0);

#pragma unroll 1
    for(int kt=0;kt<KT;kt++){
        if(kt+1<KT){
            issue(kt+1,(kt+1)&1);
            asm volatile("cp.async.wait_group 1;\n":::"memory");
        }else{
            asm volatile("cp.async.wait_group 0;\n":::"memory");
        }
        __syncthreads();

        const uint32_t st=sbase+(uint32_t)(kt&1)*STAGE;
#pragma unroll
        for(int kk=0;kk<4;kk++){
            uint32_t af[3][4], bf[3][4][2];
#pragma unroll
            for(int p=0;p<3;p++){
                {
                    uint32_t addr=st+(uint32_t)p*APL+
                        sw128((uint32_t)aRow*128+(uint32_t)(kk*16+aColL)*2);
                    asm volatile("ldmatrix.sync.aligned.m8n8.x4.shared.b16 {%0,%1,%2,%3},[%4];"
                        :"=r"(af[p][0]),"=r"(af[p][1]),
                         "=r"(af[p][2]),"=r"(af[p][3]):"r"(addr));
                }
#pragma unroll
                for(int nfb=0;nfb<4;nfb+=2){
                    uint32_t addr=st+(uint32_t)(3*APL)+(uint32_t)p*BPL+
                        sw128((uint32_t)(bRow4+nfb*8)*128+(uint32_t)(kk*16+bColL4)*2);
                    asm volatile("ldmatrix.sync.aligned.m8n8.x4.shared.b16 {%0,%1,%2,%3},[%4];"
                        :"=r"(bf[p][nfb][0]),"=r"(bf[p][nfb][1]),
                         "=r"(bf[p][nfb+1][0]),"=r"(bf[p][nfb+1][1]):"r"(addr));
                }
            }
            const int PA[6]={0,0,1,1,0,2};
            const int PB[6]={0,1,0,1,2,0};
#pragma unroll
            for(int t=0;t<6;t++){
#pragma unroll
                for(int nf=0;nf<4;nf++){
                    asm volatile(
                        "mma.sync.aligned.m16n8k16.row.col.f32.bf16.bf16.f32 "
                        "{%0,%1,%2,%3},{%4,%5,%6,%7},{%8,%9},{%0,%1,%2,%3};"
                        :"+f"(acc[nf][0]),"+f"(acc[nf][1]),
                         "+f"(acc[nf][2]),"+f"(acc[nf][3])
                        :"r"(af[PA[t]][0]),"r"(af[PA[t]][1]),
                         "r"(af[PA[t]][2]),"r"(af[PA[t]][3]),
                         "r"(bf[PB[t]][nf][0]),"r"(bf[PB[t]][nf][1]));
                }
            }
        }
        __syncthreads();
    }

    if(MODE==0){
        int row=m0+warpM*16+(lane>>2);
#pragma unroll
        for(int nf=0;nf<4;nf++){
            int col=n0+warpN*32+nf*8+(lane&3)*2;
            float b0v=bias[col], b1v=bias[col+1];
            float2 v0={acc[nf][0]+b0v, acc[nf][1]+b1v};
            float2 v1={acc[nf][2]+b0v, acc[nf][3]+b1v};
            *(float2*)(C+(size_t)row*ldc+col)=v0;
            *(float2*)(C+(size_t)(row+8)*ldc+col)=v1;
        }
    }else if(MODE==2){
        int row=m0+warpM*16+(lane>>2);
#pragma unroll
        for(int nf=0;nf<4;nf++){
            int col=n0+warpN*32+nf*8+(lane&3)*2;
            float b0v=bias[col], b1v=bias[col+1];
            float vals[4]={acc[nf][0]+b0v, acc[nf][1]+b1v,
                           acc[nf][2]+b0v, acc[nf][3]+b1v};
#pragma unroll
            for(int q=0;q<4;q++){
                int rr=row+(q>>1)*8, cc=col+(q&1);
                unsigned short s0,s1,s2; split3(vals[q],s0,s1,s2);
                size_t pos=(size_t)rr*1024+512+cc;
                ehOut[pos]=s0; ehOut[EHPS+pos]=s1; ehOut[2*EHPS+pos]=s2;
            }
        }
    }else{
        // MODE 1: gates -> smem -> fused LSTM cell (block = 64 batch x 16 hd, 4 gates)
        float* gs=(float*)sm;              // [64][68]
        constexpr int P=68;
        {
            int row=warpM*16+(lane>>2);
#pragma unroll
            for(int nf=0;nf<4;nf++){
                int col=warpN*32+nf*8+(lane&3)*2;
                gs[row*P+col]  =acc[nf][0];
                gs[row*P+col+1]=acc[nf][1];
                gs[(row+8)*P+col]  =acc[nf][2];
                gs[(row+8)*P+col+1]=acc[nf][3];
            }
        }
        __syncthreads();
#pragma unroll
        for(int i=0;i<4;i++){
            int idx=tid+i*256;             // 1024 = 64 rows x 16 hd
            int row=idx>>4, hd=idx&15;
            int hdg=bx*16+hd;
            int b=m0+row;
            float ig=gs[row*P+hd]    +bias[hdg];
            float fg=gs[row*P+16+hd] +bias[512+hdg];
            float gg=gs[row*P+32+hd] +bias[1024+hdg];
            float og=gs[row*P+48+hd] +bias[1536+hdg];
            ig=1.f/(1.f+expf(-ig));
            fg=1.f/(1.f+expf(-fg));
            gg=tanhf(gg);
            og=1.f/(1.f+expf(-og));
            size_t ci=(size_t)b*512+hdg;
            float c=fg*cState[ci]+ig*gg;
            float h=og*tanhf(c);
            cState[ci]=c;
            unsigned short s0,s1,s2; split3(h,s0,s1,s2);
            size_t pos=(size_t)b*1024+512+hdg;
            ehOut[pos]=s0; ehOut[EHPS+pos]=s1; ehOut[2*EHPS+pos]=s2;
        }
    }
}

// ---------- prep: transpose + 3-split W[Ksrc,N] -> WT planes [N][ldwt] at col kOff ----------
__global__ __launch_bounds__(1024) void trans_split_kernel(
    const float* __restrict__ W,int N,unsigned short* __restrict__ WT,
    size_t planeStride,int ldwt,int kOff)
{
    __shared__ unsigned short s[3][32][33];
    int tx=threadIdx.x&31, ty=threadIdx.x>>5;
    int n=blockIdx.x*32+tx, k=blockIdx.y*32+ty;
    unsigned short a,b,c;
    split3(W[(size_t)k*N+n],a,b,c);
    s[0][ty][tx]=a; s[1][ty][tx]=b; s[2][ty][tx]=c;
    __syncthreads();
    int on=blockIdx.x*32+ty, ok=kOff+blockIdx.y*32+tx;
#pragma unroll
    for(int p=0;p<3;p++)
        WT[p*planeStride+(size_t)on*ldwt+ok]=s[p][tx][ty];
}

__global__ void split_rows_kernel(const float* __restrict__ src,
    unsigned short* __restrict__ dst,size_t planeStride,int n)
{
    int i=blockIdx.x*blockDim.x+threadIdx.x;
    if(i>=n) return;
    unsigned short a,b,c; split3(src[i],a,b,c);
    dst[i]=a; dst[planeStride+i]=b; dst[2*planeStride+i]=c;
}

__global__ void bias_kernel(const float* __restrict__ bi,const float* __restrict__ bh)
{ int i=blockIdx.x*blockDim.x+threadIdx.x; if(i<4*NH) g_bias[i]=bi[i]+bh[i]; }

__global__ void init_kernel(const float* __restrict__ sos,unsigned short* __restrict__ ehDst)
{
    int idx=blockIdx.x*blockDim.x+threadIdx.x;
    if(idx>=NB*NE) return;
    g_c[idx]=0.f;
    int b=idx>>9, d=idx&(NE-1);
    unsigned short a,s1,s2; split3(sos[d],a,s1,s2);
    size_t pos=(size_t)b*1024+d;
    ehDst[pos]=a; ehDst[EHPS+pos]=s1; ehDst[2*EHPS+pos]=s2;
}

__global__ void eos_kernel(float* __restrict__ out)
{
    int idx=blockIdx.x*blockDim.x+threadIdx.x;
    if(idx>=NB*NV) return;
    int b=idx>>11, v=idx&(NV-1);
    out[PROBS_OFF+((size_t)b*NLP+NL)*NV+v]=1.0f;
    if(v==0){
        out[SEQ_OFF+(size_t)b*NLP+NL]=0.f;
        out[LOGP_OFF+(size_t)b*NLP+NL]=0.f;
        out[ENT_OFF+(size_t)b*NLP+NL]=0.f;
    }
}

// log_softmax + entropy + gumbel sample + pre-split embed gather into ehDst
__global__ __launch_bounds__(256) void sampler_kernel(
    const float* __restrict__ logits,float* __restrict__ out,
    int t,unsigned int sk0,unsigned int sk1,unsigned short* __restrict__ ehDst)
{
    __shared__ float row[NV];
    __shared__ float sred[256];
    __shared__ float sbest[256];
    __shared__ int sbi[256];
    __shared__ float s_max,s_lse;
    __shared__ int s_sym;
    const int b=blockIdx.x, tid=threadIdx.x;
    const float* lrow=logits+(size_t)b*NV;
    for(int v=tid;v<NV;v+=256) row[v]=lrow[v];
    __syncthreads();
    float m=-3.402823466e38f;
    for(int v=tid;v<NV;v+=256) m=fmaxf(m,row[v]);
    sred[tid]=m; __syncthreads();
    for(int s=128;s>0;s>>=1){ if(tid<s) sred[tid]=fmaxf(sred[tid],sred[tid+s]); __syncthreads(); }
    if(tid==0) s_max=sred[0];
    __syncthreads();
    const float xmax=s_max;
    float sum=0.f;
    for(int v=tid;v<NV;v+=256) sum+=expf(row[v]-xmax);
    sred[tid]=sum; __syncthreads();
    for(int s=128;s>0;s>>=1){ if(tid<s) sred[tid]+=sred[tid+s]; __syncthreads(); }
    if(tid==0) s_lse=logf(sred[0]);
    __syncthreads();
    const float lse=s_lse;
    float entacc=0.f, best=-3.402823466e38f; int besti=NV;
    float* probs_out=out+PROBS_OFF+((size_t)b*NLP+t)*NV;
    for(int v=tid;v<NV;v+=256){
        float ls=(row[v]-xmax)-lse;
        float p=expf(ls);
        probs_out[v]=p;
        entacc+=p*ls;
        unsigned int o0,o1;
        threefry2x32(sk0,sk1,0u,(unsigned int)(b*NV+v),o0,o1);
        unsigned int bits=o0^o1;
        float f=__uint_as_float((bits>>9)|0x3f800000u)-1.0f;
        float u=fmaxf(1.17549435e-38f,f+1.17549435e-38f);
        float g=-logf(-logf(u));
        float score=g+ls;
        if(score>best){best=score;besti=v;}
    }
    sred[tid]=entacc; sbest[tid]=best; sbi[tid]=besti;
    __syncthreads();
    for(int s=128;s>0;s>>=1){
        if(tid<s){
            sred[tid]+=sred[tid+s];
            float ob=sbest[tid+s]; int oi=sbi[tid+s];
            if(ob>sbest[tid]||(ob==sbest[tid]&&oi<sbi[tid])){sbest[tid]=ob;sbi[tid]=oi;}
        }
        __syncthreads();
    }
    if(tid==0){
        int sym=sbi[0]; s_sym=sym;
        out[SEQ_OFF+(size_t)b*NLP+t]=(float)sym;
        out[ENT_OFF+(size_t)b*NLP+t]=-sred[0];
        out[LOGP_OFF+(size_t)b*NLP+t]=(row[sym]-xmax)-lse;
    }
    __syncthreads();
    const int sym=s_sym;
    for(int i=tid;i<NE;i+=256){
        size_t dpos=(size_t)b*1024+i, spos=(size_t)sym*512+i;
        ehDst[dpos]=g_embS[spos];
        ehDst[EHPS+dpos]=g_embS[EPS+spos];
        ehDst[2*EHPS+dpos]=g_embS[2*EPS+spos];
    }
}

// ---------------- launch ----------------
extern "C" void kernel_launch(void* const* d_in,const int* in_sizes,int n_in,
                              void* d_out,int out_size)
{
    (void)in_sizes;(void)n_in;(void)out_size;
    const float* x        =(const float*)d_in[0];
    const float* agent_w  =(const float*)d_in[1];
    const float* agent_b  =(const float*)d_in[2];
    const float* sos      =(const float*)d_in[3];
    const float* embedding=(const float*)d_in[4];
    const float* w_ih     =(const float*)d_in[5];
    const float* w_hh     =(const float*)d_in[6];
    const float* b_ih     =(const float*)d_in[7];
    const float* b_hh     =(const float*)d_in[8];
    const float* out_w    =(const float*)d_in[9];
    const float* out_b    =(const float*)d_in[10];
    float* out=(float*)d_out;

    cudaFuncSetAttribute(gemm_mma<0>,cudaFuncAttributeMaxDynamicSharedMemorySize,GSMEM);
    cudaFuncSetAttribute(gemm_mma<1>,cudaFuncAttributeMaxDynamicSharedMemorySize,GSMEM);
    cudaFuncSetAttribute(gemm_mma<2>,cudaFuncAttributeMaxDynamicSharedMemorySize,GSMEM);

    unsigned short *pgw,*pow,*paw,*pxs,*pes;
    unsigned short *ehb[2];
    float *pb,*pc,*pl;
    cudaGetSymbolAddress((void**)&pgw,g_gatesWT);
    cudaGetSymbolAddress((void**)&pow,g_outWT);
    cudaGetSymbolAddress((void**)&paw,g_agentWT);
    cudaGetSymbolAddress((void**)&pxs,g_xS);
    cudaGetSymbolAddress((void**)&ehb[0],g_ehA);
    cudaGetSymbolAddress((void**)&ehb[1],g_ehB);
    cudaGetSymbolAddress((void**)&pes,g_embS);
    cudaGetSymbolAddress((void**)&pb,g_bias);
    cudaGetSymbolAddress((void**)&pc,g_c);
    cudaGetSymbolAddress((void**)&pl,g_logits);

    // host-side JAX key chain: key(1)=(0,1); fold-like split per step
    unsigned int key0=0u,key1=1u,sk0[NL],sk1[NL];
    for(int t=0;t<NL;t++){
        unsigned int n0,n1,s0,s1;
        threefry2x32(key0,key1,0u,0u,n0,n1);
        threefry2x32(key0,key1,0u,1u,s0,s1);
        sk0[t]=s0; sk1[t]=s1; key0=n0; key1=n1;
    }

    // prep: weight transposes + splits (per launch, deterministic)
    trans_split_kernel<<<dim3(NV/32,NE/32),1024>>>(w_ih,NV,pgw,GPS,1024,0);
    trans_split_kernel<<<dim3(NV/32,NH/32),1024>>>(w_hh,NV,pgw,GPS,1024,512);
    trans_split_kernel<<<dim3(NV/32,NH/32),1024>>>(out_w,NV,pow,OPS,512,0);
    trans_split_kernel<<<dim3(NH/32,NIN/32),1024>>>(agent_w,NH,paw,APS,1024,0);
    split_rows_kernel<<<(NB*NIN+255)/256,256>>>(x,pxs,XPS,NB*NIN);
    split_rows_kernel<<<(NV*NE+255)/256,256>>>(embedding,pes,EPS,NV*NE);
    bias_kernel<<<(4*NH+255)/256,256>>>(b_ih,b_hh);
    init_kernel<<<(NB*NE+255)/256,256>>>(sos,ehb[0]);
    eos_kernel<<<(NB*NV+255)/256,256>>>(out);

    // h0 = x @ agent_w + agent_b -> split directly into ehA h-half  [512,512], K=1024
    gemm_mma<2><<<dim3(NH/64,NB/64),256,GSMEM>>>(
        pxs,pxs+XPS,pxs+2*XPS,NIN, paw,paw+APS,paw+2*APS,1024,
        NIN,nullptr,0,agent_b,nullptr,ehb[0]);

    for(int t=0;t<NL;t++){
        unsigned short* ein=ehb[t&1];        // e_t | h_t
        unsigned short* eout=ehb[(t+1)&1];   // gets h_{t+1-cell output} and e_{t+1}
        // gates GEMM + fused LSTM cell: [e|h] @ [w_ih;w_hh]^T + bias, K=1024
        // reads ein (both halves), writes split-h_t' into eout h-half  (no hazard)
        gemm_mma<1><<<dim3(32,NB/64),256,GSMEM>>>(
            ein,ein+EHPS,ein+2*EHPS,1024, pgw,pgw+GPS,pgw+2*GPS,1024,
            1024,nullptr,0,pb,pc,eout);
        // logits = h @ out_w^T + out_b -> [512,2048], K=512  (h from eout)
        gemm_mma<0><<<dim3(NV/64,NB/64),256,GSMEM>>>(
            eout+512,eout+EHPS+512,eout+2*EHPS+512,1024, pow,pow+OPS,pow+2*OPS,512,
            512,pl,NV,out_b,nullptr,nullptr);
        // sampler writes e_{t+1} into eout e-half
        sampler_kernel<<<NB,256>>>(pl,out,t,sk0[t],sk1[t],eout);
    }
}

// round 17
// speedup vs baseline: 3.4034x; 1.2528x over previous
#include <cuda_runtime.h>
#include <cuda_bf16.h>
#include <cstdint>

constexpr int NB=512, NH=512, NE=512, NV=2048, NIN=1024, NL=32, NLP=33;
constexpr size_t SEQ_OFF=0;
constexpr size_t PROBS_OFF=(size_t)NB*NLP;
constexpr size_t LOGP_OFF=PROBS_OFF+(size_t)NB*NLP*NV;
constexpr size_t ENT_OFF=LOGP_OFF+(size_t)NB*NLP;

// plane strides (elements)
constexpr size_t GPS=(size_t)NV*1024;   // gatesWT [2048][1024] (w_ih cols 0-511 | w_hh cols 512-1023)
constexpr size_t OPS=(size_t)NV*512;    // outWT   [2048][512]
constexpr size_t APS=(size_t)NH*1024;   // agentWT [512][1024]
constexpr size_t XPS=(size_t)NB*NIN;    // xS      [512][1024]
constexpr size_t HPS=(size_t)NB*NH;     // hS      [512][512]
constexpr size_t EPS=(size_t)NV*NE;     // embS    [2048][512]

__device__ __align__(16) unsigned short g_gatesWT[3*GPS];
__device__ __align__(16) unsigned short g_outWT[3*OPS];
__device__ __align__(16) unsigned short g_agentWT[3*APS];
__device__ __align__(16) unsigned short g_xS[3*XPS];
__device__ __align__(16) unsigned short g_hA[3*HPS];   // ping
__device__ __align__(16) unsigned short g_hB[3*HPS];   // pong
__device__ __align__(16) unsigned short g_embS[3*EPS];
__device__ float g_table[(size_t)(NV+1)*2048];  // emb@w_ih+bias, row 2048 = sos@w_ih+bias
__device__ float g_bias[4*NH];
__device__ float g_c[NB*NH];
__device__ int   g_sym[NB];
__device__ float g_logits[NB*NV];

__device__ __forceinline__ void split3(float v, unsigned short& o0,
                                       unsigned short& o1, unsigned short& o2)
{
    __nv_bfloat16 b0=__float2bfloat16_rn(v);
    float r=v-__bfloat162float(b0);
    __nv_bfloat16 b1=__float2bfloat16_rn(r);
    float r2=r-__bfloat162float(b1);
    __nv_bfloat16 b2=__float2bfloat16_rn(r2);
    o0=__bfloat16_as_ushort(b0); o1=__bfloat16_as_ushort(b1); o2=__bfloat16_as_ushort(b2);
}

// ---------- threefry2x32 (JAX-exact, verified) ----------
#define TF_ROTL(x,d) (((x)<<(d))|((x)>>(32-(d))))
#define TF_ROUND(r) { x0+=x1; x1=TF_ROTL(x1,r); x1^=x0; }
__host__ __device__ __forceinline__ void threefry2x32(
    unsigned int k0,unsigned int k1,unsigned int x0,unsigned int x1,
    unsigned int& o0,unsigned int& o1)
{
    unsigned int ks0=k0,ks1=k1,ks2=k0^k1^0x1BD11BDAu;
    x0+=ks0; x1+=ks1;
    TF_ROUND(13) TF_ROUND(15) TF_ROUND(26) TF_ROUND(6)
    x0+=ks1; x1+=ks2+1u;
    TF_ROUND(17) TF_ROUND(29) TF_ROUND(16) TF_ROUND(24)
    x0+=ks2; x1+=ks0+2u;
    TF_ROUND(13) TF_ROUND(15) TF_ROUND(26) TF_ROUND(6)
    x0+=ks0; x1+=ks1+3u;
    TF_ROUND(17) TF_ROUND(29) TF_ROUND(16) TF_ROUND(24)
    x0+=ks1; x1+=ks2+4u;
    TF_ROUND(13) TF_ROUND(15) TF_ROUND(26) TF_ROUND(6)
    x0+=ks2; x1+=ks0+5u;
    o0=x0; o1=x1;
}

__device__ __forceinline__ uint32_t smem_u32(const void* p)
{ uint32_t a; asm("{ .reg .u64 t; cvta.to.shared.u64 t, %1; cvt.u32.u64 %0, t; }":"=r"(a):"l"(p)); return a; }

__device__ __forceinline__ uint32_t sw128(uint32_t off)
{ return off ^ ((off >> 3) & 0x70u); }

// ---------- portable tensor-core bf16x3 GEMM (mma.sync, sm_80+ ISA) ----------
// C[M,N] fp32 = sum_{6 split products} A[M,K] * B[N,K]^T (+ per-mode epilogue)
// Block tile 64(M) x 64(N), 8 warps (4Mx2N), warp tile 16x32, K staged 64-wide.
// MODE 0: plain store C + bias
// MODE 1: gate-interleaved N mapping (n = gate*512 + bx*16 + j); epilogue adds
//         table[symArr[b]] row (contains e@w_ih + bias), runs LSTM cell,
//         writes split-h into hOut (pong buffer)
// MODE 2: h0: epilogue writes split3(acc+bias) into hOut
constexpr int APL   = 64*64*2;            // 8192 B per A plane tile
constexpr int BPL   = 64*64*2;            // 8192 B per B plane tile
constexpr int STAGE = 3*APL + 3*BPL;      // 49152 B
constexpr int GSMEM = 2*STAGE;            // 98304 B

template<int MODE>
__global__ __launch_bounds__(256,2) void gemm_mma(
    const unsigned short* __restrict__ a0,const unsigned short* __restrict__ a1,
    const unsigned short* __restrict__ a2,int lda,
    const unsigned short* __restrict__ b0,const unsigned short* __restrict__ b1,
    const unsigned short* __restrict__ b2,int ldb,
    int K,float* __restrict__ C,int ldc,const float* __restrict__ bias,
    float* __restrict__ cState,unsigned short* __restrict__ hOut,
    const float* __restrict__ table,const int* __restrict__ symArr)
{
    extern __shared__ char sm[];
    const int tid=threadIdx.x, wid=tid>>5, lane=tid&31;
    const int bx=blockIdx.x;
    const int m0=blockIdx.y*64, n0=bx*64;
    const int warpM=wid&3, warpN=wid>>2;       // 4 x 2 warps
    const uint32_t sbase=smem_u32(sm);
    const unsigned short* Ap[3]={a0,a1,a2};
    const unsigned short* Bp[3]={b0,b1,b2};
    const int KT=K>>6;

    float acc[4][4];                            // nf x 4 (warp tile 16x32)
#pragma unroll
    for(int j=0;j<4;j++)
#pragma unroll
        for(int k=0;k<4;k++) acc[j][k]=0.f;

    // ldmatrix lane-address components (within-tile)
    const int aRow = warpM*16 + (lane&7) + ((lane>>3)&1)*8;
    const int aColL = ((lane>>4)&1)*8;                        // + kk*16
    const int bRow4 = warpN*32 + ((lane>>4)&1)*8 + (lane&7);  // + nfb*8
    const int bColL4 = ((lane>>3)&1)*8;                       // + kk*16

    // ---- cp.async stage issue ----
    auto issue=[&](int kt,int buf){
        uint32_t st=sbase+(uint32_t)buf*STAGE;
#pragma unroll
        for(int i=0;i<6;i++){          // A planes: 3 x 512 chunks
            int idx=tid+i*256;
            int p=idx>>9, rem=idx&511, r=rem>>3, c8=rem&7;
            const unsigned short* g=Ap[p]+(size_t)(m0+r)*lda+kt*64+c8*8;
            uint32_t so=(uint32_t)p*APL + sw128((uint32_t)r*128+(uint32_t)c8*16);
            asm volatile("cp.async.cg.shared.global [%0],[%1],16;\n"
                         ::"r"(st+so),"l"(g));
        }
#pragma unroll
        for(int i=0;i<6;i++){          // B planes: 3 x 512 chunks
            int idx=tid+i*256;
            int p=idx>>9, rem=idx&511, r=rem>>3, c8=rem&7;
            int srcN = (MODE==1) ? (((r>>4)<<9) + bx*16 + (r&15)) : (n0 + r);
            const unsigned short* g=Bp[p]+(size_t)srcN*ldb+kt*64+c8*8;
            uint32_t so=(uint32_t)(3*APL)+(uint32_t)p*BPL + sw128((uint32_t)r*128+(uint32_t)c8*16);
            asm volatile("cp.async.cg.shared.global [%0],[%1],16;\n"
                         ::"r"(st+so),"l"(g));
        }
        asm volatile("cp.async.commit_group;\n":::"memory");
    };

    issue(0,0);

#pragma unroll 1
    for(int kt=0;kt<KT;kt++){
        if(kt+1<KT){
            issue(kt+1,(kt+1)&1);
            asm volatile("cp.async.wait_group 1;\n":::"memory");
        }else{
            asm volatile("cp.async.wait_group 0;\n":::"memory");
        }
        __syncthreads();

        const uint32_t st=sbase+(uint32_t)(kt&1)*STAGE;
#pragma unroll
        for(int kk=0;kk<4;kk++){
            uint32_t af[3][4], bf[3][4][2];
#pragma unroll
            for(int p=0;p<3;p++){
                {
                    uint32_t addr=st+(uint32_t)p*APL+
                        sw128((uint32_t)aRow*128+(uint32_t)(kk*16+aColL)*2);
                    asm volatile("ldmatrix.sync.aligned.m8n8.x4.shared.b16 {%0,%1,%2,%3},[%4];"
                        :"=r"(af[p][0]),"=r"(af[p][1]),
                         "=r"(af[p][2]),"=r"(af[p][3]):"r"(addr));
                }
#pragma unroll
                for(int nfb=0;nfb<4;nfb+=2){
                    uint32_t addr=st+(uint32_t)(3*APL)+(uint32_t)p*BPL+
                        sw128((uint32_t)(bRow4+nfb*8)*128+(uint32_t)(kk*16+bColL4)*2);
                    asm volatile("ldmatrix.sync.aligned.m8n8.x4.shared.b16 {%0,%1,%2,%3},[%4];"
                        :"=r"(bf[p][nfb][0]),"=r"(bf[p][nfb][1]),
                         "=r"(bf[p][nfb+1][0]),"=r"(bf[p][nfb+1][1]):"r"(addr));
                }
            }
            const int PA[6]={0,0,1,1,0,2};
            const int PB[6]={0,1,0,1,2,0};
#pragma unroll
            for(int t=0;t<6;t++){
#pragma unroll
                for(int nf=0;nf<4;nf++){
                    asm volatile(
                        "mma.sync.aligned.m16n8k16.row.col.f32.bf16.bf16.f32 "
                        "{%0,%1,%2,%3},{%4,%5,%6,%7},{%8,%9},{%0,%1,%2,%3};"
                        :"+f"(acc[nf][0]),"+f"(acc[nf][1]),
                         "+f"(acc[nf][2]),"+f"(acc[nf][3])
                        :"r"(af[PA[t]][0]),"r"(af[PA[t]][1]),
                         "r"(af[PA[t]][2]),"r"(af[PA[t]][3]),
                         "r"(bf[PB[t]][nf][0]),"r"(bf[PB[t]][nf][1]));
                }
            }
        }
        __syncthreads();
    }

    if(MODE==0){
        int row=m0+warpM*16+(lane>>2);
#pragma unroll
        for(int nf=0;nf<4;nf++){
            int col=n0+warpN*32+nf*8+(lane&3)*2;
            float b0v=bias[col], b1v=bias[col+1];
            float2 v0={acc[nf][0]+b0v, acc[nf][1]+b1v};
            float2 v1={acc[nf][2]+b0v, acc[nf][3]+b1v};
            *(float2*)(C+(size_t)row*ldc+col)=v0;
            *(float2*)(C+(size_t)(row+8)*ldc+col)=v1;
        }
    }else if(MODE==2){
        int row=m0+warpM*16+(lane>>2);
#pragma unroll
        for(int nf=0;nf<4;nf++){
            int col=n0+warpN*32+nf*8+(lane&3)*2;
            float b0v=bias[col], b1v=bias[col+1];
            float vals[4]={acc[nf][0]+b0v, acc[nf][1]+b1v,
                           acc[nf][2]+b0v, acc[nf][3]+b1v};
#pragma unroll
            for(int q=0;q<4;q++){
                int rr=row+(q>>1)*8, cc=col+(q&1);
                unsigned short s0,s1,s2; split3(vals[q],s0,s1,s2);
                size_t pos=(size_t)rr*512+cc;
                hOut[pos]=s0; hOut[HPS+pos]=s1; hOut[2*HPS+pos]=s2;
            }
        }
    }else{
        // MODE 1: gates(h-part) -> smem; add table[sym] (e-part+bias); LSTM cell
        float* gs=(float*)sm;              // [64][68]
        constexpr int P=68;
        {
            int row=warpM*16+(lane>>2);
#pragma unroll
            for(int nf=0;nf<4;nf++){
                int col=warpN*32+nf*8+(lane&3)*2;
                gs[row*P+col]  =acc[nf][0];
                gs[row*P+col+1]=acc[nf][1];
                gs[(row+8)*P+col]  =acc[nf][2];
                gs[(row+8)*P+col+1]=acc[nf][3];
            }
        }
        __syncthreads();
#pragma unroll
        for(int i=0;i<4;i++){
            int idx=tid+i*256;             // 1024 = 64 rows x 16 hd
            int row=idx>>4, hd=idx&15;
            int hdg=bx*16+hd;
            int b=m0+row;
            const float* trow=table+(size_t)symArr[b]*2048;
            float ig=gs[row*P+hd]    +trow[hdg];
            float fg=gs[row*P+16+hd] +trow[512+hdg];
            float gg=gs[row*P+32+hd] +trow[1024+hdg];
            float og=gs[row*P+48+hd] +trow[1536+hdg];
            ig=1.f/(1.f+expf(-ig));
            fg=1.f/(1.f+expf(-fg));
            gg=tanhf(gg);
            og=1.f/(1.f+expf(-og));
            size_t ci=(size_t)b*512+hdg;
            float c=fg*cState[ci]+ig*gg;
            float h=og*tanhf(c);
            cState[ci]=c;
            unsigned short s0,s1,s2; split3(h,s0,s1,s2);
            size_t pos=(size_t)b*512+hdg;
            hOut[pos]=s0; hOut[HPS+pos]=s1; hOut[2*HPS+pos]=s2;
        }
    }
}

// ---------- prep: transpose + 3-split W[Ksrc,N] -> WT planes [N][ldwt] at col kOff ----------
__global__ __launch_bounds__(1024) void trans_split_kernel(
    const float* __restrict__ W,int N,unsigned short* __restrict__ WT,
    size_t planeStride,int ldwt,int kOff)
{
    __shared__ unsigned short s[3][32][33];
    int tx=threadIdx.x&31, ty=threadIdx.x>>5;
    int n=blockIdx.x*32+tx, k=blockIdx.y*32+ty;
    unsigned short a,b,c;
    split3(W[(size_t)k*N+n],a,b,c);
    s[0][ty][tx]=a; s[1][ty][tx]=b; s[2][ty][tx]=c;
    __syncthreads();
    int on=blockIdx.x*32+ty, ok=kOff+blockIdx.y*32+tx;
#pragma unroll
    for(int p=0;p<3;p++)
        WT[p*planeStride+(size_t)on*ldwt+ok]=s[p][tx][ty];
}

__global__ void split_rows_kernel(const float* __restrict__ src,
    unsigned short* __restrict__ dst,size_t planeStride,int n)
{
    int i=blockIdx.x*blockDim.x+threadIdx.x;
    if(i>=n) return;
    unsigned short a,b,c; split3(src[i],a,b,c);
    dst[i]=a; dst[planeStride+i]=b; dst[2*planeStride+i]=c;
}

__global__ void bias_kernel(const float* __restrict__ bi,const float* __restrict__ bh)
{ int i=blockIdx.x*blockDim.x+threadIdx.x; if(i<4*NH) g_bias[i]=bi[i]+bh[i]; }

// c=0, sym=2048 (points to sos row of table)
__global__ void init_kernel()
{
    int idx=blockIdx.x*blockDim.x+threadIdx.x;
    if(idx<NB*NH) g_c[idx]=0.f;
    if(idx<NB) g_sym[idx]=NV;
}

// table row NV = sos @ w_ih + (b_ih + b_hh)
__global__ void sosrow_kernel(const float* __restrict__ sos,
                              const float* __restrict__ w_ih)
{
    int n=blockIdx.x*blockDim.x+threadIdx.x;
    if(n>=2048) return;
    float acc=g_bias[n];
    for(int k=0;k<NE;k++) acc+=sos[k]*w_ih[(size_t)k*2048+n];
    g_table[(size_t)NV*2048+n]=acc;
}

__global__ void eos_kernel(float* __restrict__ out)
{
    int idx=blockIdx.x*blockDim.x+threadIdx.x;
    if(idx>=NB*NV) return;
    int b=idx>>11, v=idx&(NV-1);
    out[PROBS_OFF+((size_t)b*NLP+NL)*NV+v]=1.0f;
    if(v==0){
        out[SEQ_OFF+(size_t)b*NLP+NL]=0.f;
        out[LOGP_OFF+(size_t)b*NLP+NL]=0.f;
        out[ENT_OFF+(size_t)b*NLP+NL]=0.f;
    }
}

// log_softmax + entropy + gumbel sample; writes sym for next step's gates
__global__ __launch_bounds__(256) void sampler_kernel(
    const float* __restrict__ logits,float* __restrict__ out,
    int t,unsigned int sk0,unsigned int sk1)
{
    __shared__ float row[NV];
    __shared__ float sred[256];
    __shared__ float sbest[256];
    __shared__ int sbi[256];
    __shared__ float s_max,s_lse;
    const int b=blockIdx.x, tid=threadIdx.x;
    const float* lrow=logits+(size_t)b*NV;
    for(int v=tid;v<NV;v+=256) row[v]=lrow[v];
    __syncthreads();
    float m=-3.402823466e38f;
    for(int v=tid;v<NV;v+=256) m=fmaxf(m,row[v]);
    sred[tid]=m; __syncthreads();
    for(int s=128;s>0;s>>=1){ if(tid<s) sred[tid]=fmaxf(sred[tid],sred[tid+s]); __syncthreads(); }
    if(tid==0) s_max=sred[0];
    __syncthreads();
    const float xmax=s_max;
    float sum=0.f;
    for(int v=tid;v<NV;v+=256) sum+=expf(row[v]-xmax);
    sred[tid]=sum; __syncthreads();
    for(int s=128;s>0;s>>=1){ if(tid<s) sred[tid]+=sred[tid+s]; __syncthreads(); }
    if(tid==0) s_lse=logf(sred[0]);
    __syncthreads();
    const float lse=s_lse;
    float entacc=0.f, best=-3.402823466e38f; int besti=NV;
    float* probs_out=out+PROBS_OFF+((size_t)b*NLP+t)*NV;
    for(int v=tid;v<NV;v+=256){
        float ls=(row[v]-xmax)-lse;
        float p=expf(ls);
        probs_out[v]=p;
        entacc+=p*ls;
        unsigned int o0,o1;
        threefry2x32(sk0,sk1,0u,(unsigned int)(b*NV+v),o0,o1);
        unsigned int bits=o0^o1;
        float f=__uint_as_float((bits>>9)|0x3f800000u)-1.0f;
        float u=fmaxf(1.17549435e-38f,f+1.17549435e-38f);
        float g=-logf(-logf(u));
        float score=g+ls;
        if(score>best){best=score;besti=v;}
    }
    sred[tid]=entacc; sbest[tid]=best; sbi[tid]=besti;
    __syncthreads();
    for(int s=128;s>0;s>>=1){
        if(tid<s){
            sred[tid]+=sred[tid+s];
            float ob=sbest[tid+s]; int oi=sbi[tid+s];
            if(ob>sbest[tid]||(ob==sbest[tid]&&oi<sbi[tid])){sbest[tid]=ob;sbi[tid]=oi;}
        }
        __syncthreads();
    }
    if(tid==0){
        int sym=sbi[0];
        g_sym[b]=sym;
        out[SEQ_OFF+(size_t)b*NLP+t]=(float)sym;
        out[ENT_OFF+(size_t)b*NLP+t]=-sred[0];
        out[LOGP_OFF+(size_t)b*NLP+t]=(row[sym]-xmax)-lse;
    }
}

// ---------------- launch ----------------
extern "C" void kernel_launch(void* const* d_in,const int* in_sizes,int n_in,
                              void* d_out,int out_size)
{
    (void)in_sizes;(void)n_in;(void)out_size;
    const float* x        =(const float*)d_in[0];
    const float* agent_w  =(const float*)d_in[1];
    const float* agent_b  =(const float*)d_in[2];
    const float* sos      =(const float*)d_in[3];
    const float* embedding=(const float*)d_in[4];
    const float* w_ih     =(const float*)d_in[5];
    const float* w_hh     =(const float*)d_in[6];
    const float* b_ih     =(const float*)d_in[7];
    const float* b_hh     =(const float*)d_in[8];
    const float* out_w    =(const float*)d_in[9];
    const float* out_b    =(const float*)d_in[10];
    float* out=(float*)d_out;

    cudaFuncSetAttribute(gemm_mma<0>,cudaFuncAttributeMaxDynamicSharedMemorySize,GSMEM);
    cudaFuncSetAttribute(gemm_mma<1>,cudaFuncAttributeMaxDynamicSharedMemorySize,GSMEM);
    cudaFuncSetAttribute(gemm_mma<2>,cudaFuncAttributeMaxDynamicSharedMemorySize,GSMEM);

    unsigned short *pgw,*pow,*paw,*pxs,*pes;
    unsigned short *hb[2];
    float *pb,*pc,*pl,*pt;
    int *psym;
    cudaGetSymbolAddress((void**)&pgw,g_gatesWT);
    cudaGetSymbolAddress((void**)&pow,g_outWT);
    cudaGetSymbolAddress((void**)&paw,g_agentWT);
    cudaGetSymbolAddress((void**)&pxs,g_xS);
    cudaGetSymbolAddress((void**)&hb[0],g_hA);
    cudaGetSymbolAddress((void**)&hb[1],g_hB);
    cudaGetSymbolAddress((void**)&pes,g_embS);
    cudaGetSymbolAddress((void**)&pb,g_bias);
    cudaGetSymbolAddress((void**)&pc,g_c);
    cudaGetSymbolAddress((void**)&pl,g_logits);
    cudaGetSymbolAddress((void**)&pt,g_table);
    cudaGetSymbolAddress((void**)&psym,g_sym);

    // host-side JAX key chain: key(1)=(0,1); fold-like split per step
    unsigned int key0=0u,key1=1u,sk0[NL],sk1[NL];
    for(int t=0;t<NL;t++){
        unsigned int n0,n1,s0,s1;
        threefry2x32(key0,key1,0u,0u,n0,n1);
        threefry2x32(key0,key1,0u,1u,s0,s1);
        sk0[t]=s0; sk1[t]=s1; key0=n0; key1=n1;
    }

    // prep: weight transposes + splits (per launch, deterministic)
    trans_split_kernel<<<dim3(NV/32,NE/32),1024>>>(w_ih,NV,pgw,GPS,1024,0);
    trans_split_kernel<<<dim3(NV/32,NH/32),1024>>>(w_hh,NV,pgw,GPS,1024,512);
    trans_split_kernel<<<dim3(NV/32,NH/32),1024>>>(out_w,NV,pow,OPS,512,0);
    trans_split_kernel<<<dim3(NH/32,NIN/32),1024>>>(agent_w,NH,paw,APS,1024,0);
    split_rows_kernel<<<(NB*NIN+255)/256,256>>>(x,pxs,XPS,NB*NIN);
    split_rows_kernel<<<(NV*NE+255)/256,256>>>(embedding,pes,EPS,NV*NE);
    bias_kernel<<<(4*NH+255)/256,256>>>(b_ih,b_hh);
    init_kernel<<<(NB*NH+255)/256,256>>>();
    eos_kernel<<<(NB*NV+255)/256,256>>>(out);

    // emb-logits table: embedding @ w_ih + bias -> [2048,2048]  (K=512, one-time)
    gemm_mma<0><<<dim3(2048/64,NV/64),256,GSMEM>>>(
        pes,pes+EPS,pes+2*EPS,512, pgw,pgw+GPS,pgw+2*GPS,1024,
        512,pt,2048,pb,nullptr,nullptr,nullptr,nullptr);
    sosrow_kernel<<<8,256>>>(sos,w_ih);

    // h0 = x @ agent_w + agent_b -> split into hA  [512,512], K=1024
    gemm_mma<2><<<dim3(NH/64,NB/64),256,GSMEM>>>(
        pxs,pxs+XPS,pxs+2*XPS,NIN, paw,paw+APS,paw+2*APS,1024,
        NIN,nullptr,0,agent_b,nullptr,hb[0],nullptr,nullptr);

    for(int t=0;t<NL;t++){
        unsigned short* hin=hb[t&1];
        unsigned short* hout=hb[(t+1)&1];
        // gates = h @ w_hh^T (+ table[sym] with e-part+bias) + fused cell, K=512
        gemm_mma<1><<<dim3(32,NB/64),256,GSMEM>>>(
            hin,hin+HPS,hin+2*HPS,512, pgw+512,pgw+GPS+512,pgw+2*GPS+512,1024,
            512,nullptr,0,nullptr,pc,hout,pt,psym);
        // logits = h' @ out_w^T + out_b -> [512,2048], K=512
        gemm_mma<0><<<dim3(NV/64,NB/64),256,GSMEM>>>(
            hout,hout+HPS,hout+2*HPS,512, pow,pow+OPS,pow+2*OPS,512,
            512,pl,NV,out_b,nullptr,nullptr,nullptr,nullptr);
        // sampler writes g_sym for step t+1
        sampler_kernel<<<NB,256>>>(pl,out,t,sk0[t],sk1[t]);
    }
}